// round 1
// baseline (speedup 1.0000x reference)
#include <cuda_runtime.h>
#include <math.h>

#define DMODEL 512
#define NHEAD 8
#define HD 64
#define MAXS 4096

// Scratch (no allocations allowed) — __device__ globals.
__device__ float g_Q[MAXS * DMODEL];
__device__ float g_K[MAXS * DMODEL];
__device__ float g_V[MAXS * DMODEL];
__device__ float g_AO[MAXS * DMODEL];
__device__ float g_T1[MAXS * DMODEL];

__device__ __forceinline__ float dot4(float4 a, float4 b) {
    return a.x * b.x + a.y * b.y + a.z * b.z + a.w * b.w;
}
__device__ __forceinline__ void fma4(float4& c, float a, float4 b) {
    c.x += a * b.x; c.y += a * b.y; c.z += a * b.z; c.w += a * b.w;
}

// ============================================================================
// SGEMM: C[M,N] = A[M,K] @ B[K,N] (+ bias per output column, optional)
// BM=128, BN=128, BK=16, 256 threads, 8x8 per thread (2x2 quadrants of 4x4)
// ============================================================================
__global__ __launch_bounds__(256) void sgemm_kernel(
    const float* __restrict__ A, const float* __restrict__ B,
    float* __restrict__ C, const float* __restrict__ bias,
    int M, int N, int K)
{
    __shared__ float As[16 * 132];  // transposed A tile, padded stride
    __shared__ float Bs[16 * 132];

    const int tid = threadIdx.x;
    const int tx = tid & 15, ty = tid >> 4;
    const int bm = blockIdx.y << 7, bn = blockIdx.x << 7;

    float4 acc[8][2];
#pragma unroll
    for (int i = 0; i < 8; i++) {
        acc[i][0] = make_float4(0.f, 0.f, 0.f, 0.f);
        acc[i][1] = make_float4(0.f, 0.f, 0.f, 0.f);
    }

    for (int k0 = 0; k0 < K; k0 += 16) {
        // Load A tile (128 x 16), store transposed As[k][m]
#pragma unroll
        for (int f = tid; f < 512; f += 256) {
            int r = f >> 2, c4 = (f & 3) << 2;
            float4 v = *(const float4*)(A + (size_t)(bm + r) * K + k0 + c4);
            As[(c4 + 0) * 132 + r] = v.x;
            As[(c4 + 1) * 132 + r] = v.y;
            As[(c4 + 2) * 132 + r] = v.z;
            As[(c4 + 3) * 132 + r] = v.w;
        }
        // Load B tile (16 x 128)
#pragma unroll
        for (int f = tid; f < 512; f += 256) {
            int r = f >> 5, c4 = (f & 31) << 2;
            *(float4*)(Bs + r * 132 + c4) =
                *(const float4*)(B + (size_t)(k0 + r) * N + bn + c4);
        }
        __syncthreads();

#pragma unroll
        for (int k = 0; k < 16; k++) {
            float4 aL = *(const float4*)(As + k * 132 + (ty << 2));
            float4 aH = *(const float4*)(As + k * 132 + 64 + (ty << 2));
            float4 bL = *(const float4*)(Bs + k * 132 + (tx << 2));
            float4 bH = *(const float4*)(Bs + k * 132 + 64 + (tx << 2));
            float av[8] = { aL.x, aL.y, aL.z, aL.w, aH.x, aH.y, aH.z, aH.w };
#pragma unroll
            for (int i = 0; i < 8; i++) {
                fma4(acc[i][0], av[i], bL);
                fma4(acc[i][1], av[i], bH);
            }
        }
        __syncthreads();
    }

    // Epilogue
#pragma unroll
    for (int i = 0; i < 8; i++) {
        int rloc = (i < 4) ? ((ty << 2) + i) : (64 + (ty << 2) + i - 4);
        int r = bm + rloc;
#pragma unroll
        for (int jq = 0; jq < 2; jq++) {
            int c = bn + (jq << 6) + (tx << 2);
            float4 v = acc[i][jq];
            if (bias) {
                v.x += bias[c + 0];
                v.y += bias[c + 1];
                v.z += bias[c + 2];
                v.w += bias[c + 3];
            }
            *(float4*)(C + (size_t)r * N + c) = v;
        }
    }
}

// ============================================================================
// Fused flash attention: per block, one head x 64 queries; loop over key tiles
// of 64. 256 threads (16x16), 4x4 S-tile per thread, online softmax.
// Smem: Qs / KPs (K tile, reused for P) / Vs = 3 x 16KB = 48KB exactly.
// XOR chunk swizzle breaks stride-64 bank conflicts.
// ============================================================================
__global__ __launch_bounds__(256) void attn_kernel(
    const float* __restrict__ Q, const float* __restrict__ K,
    const float* __restrict__ V, float* __restrict__ O, int S)
{
    __shared__ float Qs[64 * 64];
    __shared__ float KPs[64 * 64];
    __shared__ float Vs[64 * 64];

    const int tid = threadIdx.x;
    const int tx = tid & 15, ty = tid >> 4;
    const int head = blockIdx.y;
    const int q0 = blockIdx.x << 6;

    // Load Q tile, pre-scaled by 1/sqrt(DK) = 1/8
    const float* Qg = Q + (size_t)q0 * DMODEL + head * HD;
#pragma unroll
    for (int f = tid; f < 1024; f += 256) {
        int r = f >> 4, c4 = f & 15;
        float4 v = *(const float4*)(Qg + (size_t)r * DMODEL + (c4 << 2));
        v.x *= 0.125f; v.y *= 0.125f; v.z *= 0.125f; v.w *= 0.125f;
        *(float4*)(Qs + (r << 6) + (((c4 ^ (r & 15))) << 2)) = v;
    }

    float m[4], l[4];
    float4 accv[4];
#pragma unroll
    for (int i = 0; i < 4; i++) {
        m[i] = -1e30f; l[i] = 0.f;
        accv[i] = make_float4(0.f, 0.f, 0.f, 0.f);
    }

    const int nkb = S >> 6;
    for (int kb = 0; kb < nkb; kb++) {
        const float* Kg = K + (size_t)(kb << 6) * DMODEL + head * HD;
        const float* Vg = V + (size_t)(kb << 6) * DMODEL + head * HD;
        __syncthreads();   // previous iteration fully done with KPs/Vs
#pragma unroll
        for (int f = tid; f < 1024; f += 256) {
            int r = f >> 4, c4 = f & 15;
            int off = (r << 6) + (((c4 ^ (r & 15))) << 2);
            *(float4*)(KPs + off) = *(const float4*)(Kg + (size_t)r * DMODEL + (c4 << 2));
            *(float4*)(Vs + off)  = *(const float4*)(Vg + (size_t)r * DMODEL + (c4 << 2));
        }
        __syncthreads();

        // S = Qtile @ Ktile^T  (64x64, 4x4 per thread)
        float s[4][4];
#pragma unroll
        for (int i = 0; i < 4; i++)
#pragma unroll
            for (int j = 0; j < 4; j++) s[i][j] = 0.f;

#pragma unroll
        for (int d4 = 0; d4 < 16; d4++) {
            float4 a[4], b[4];
#pragma unroll
            for (int i = 0; i < 4; i++) {
                int r = (ty << 2) + i;
                a[i] = *(const float4*)(Qs + (r << 6) + (((d4 ^ (r & 15))) << 2));
            }
#pragma unroll
            for (int j = 0; j < 4; j++) {
                int c = (tx << 2) + j;
                b[j] = *(const float4*)(KPs + (c << 6) + (((d4 ^ (c & 15))) << 2));
            }
#pragma unroll
            for (int i = 0; i < 4; i++)
#pragma unroll
                for (int j = 0; j < 4; j++) s[i][j] += dot4(a[i], b[j]);
        }

        // Online softmax update. Row owned by the 16 threads with same ty:
        // lanes (ty&1)*16 + tx, so xor 1/2/4/8 stays in-group.
#pragma unroll
        for (int i = 0; i < 4; i++) {
            float bm = fmaxf(fmaxf(s[i][0], s[i][1]), fmaxf(s[i][2], s[i][3]));
#pragma unroll
            for (int o = 1; o < 16; o <<= 1)
                bm = fmaxf(bm, __shfl_xor_sync(0xffffffffu, bm, o));
            float mnew = fmaxf(m[i], bm);
            float alpha = __expf(m[i] - mnew);
            float sum = 0.f;
#pragma unroll
            for (int j = 0; j < 4; j++) {
                s[i][j] = __expf(s[i][j] - mnew);
                sum += s[i][j];
            }
#pragma unroll
            for (int o = 1; o < 16; o <<= 1)
                sum += __shfl_xor_sync(0xffffffffu, sum, o);
            l[i] = l[i] * alpha + sum;
            m[i] = mnew;
            accv[i].x *= alpha; accv[i].y *= alpha;
            accv[i].z *= alpha; accv[i].w *= alpha;
        }

        __syncthreads();   // everyone finished reading K from KPs
        // Store P into KPs
#pragma unroll
        for (int i = 0; i < 4; i++) {
            int r = (ty << 2) + i;
            float4 pv = make_float4(s[i][0], s[i][1], s[i][2], s[i][3]);
            *(float4*)(KPs + (r << 6) + (((tx ^ (r & 15))) << 2)) = pv;
        }
        __syncthreads();

        // O += P @ Vtile   (64x64 x 64x64)
#pragma unroll
        for (int k4 = 0; k4 < 16; k4++) {
            float4 pa[4], vb[4];
#pragma unroll
            for (int i = 0; i < 4; i++) {
                int r = (ty << 2) + i;
                pa[i] = *(const float4*)(KPs + (r << 6) + (((k4 ^ (r & 15))) << 2));
            }
#pragma unroll
            for (int kk = 0; kk < 4; kk++) {
                int kr = (k4 << 2) + kk;
                vb[kk] = *(const float4*)(Vs + (kr << 6) + (((tx ^ (kr & 15))) << 2));
            }
#pragma unroll
            for (int i = 0; i < 4; i++) {
                fma4(accv[i], pa[i].x, vb[0]);
                fma4(accv[i], pa[i].y, vb[1]);
                fma4(accv[i], pa[i].z, vb[2]);
                fma4(accv[i], pa[i].w, vb[3]);
            }
        }
    }

    // Epilogue: normalize and write [q0+r, head*64 + tx*4 ..]
    float* Og = O + (size_t)q0 * DMODEL + head * HD;
#pragma unroll
    for (int i = 0; i < 4; i++) {
        int r = (ty << 2) + i;
        float inv = 1.0f / l[i];
        float4 v = make_float4(accv[i].x * inv, accv[i].y * inv,
                               accv[i].z * inv, accv[i].w * inv);
        *(float4*)(Og + (size_t)r * DMODEL + (tx << 2)) = v;
    }
}

// ============================================================================
// kernel_launch
// ============================================================================
extern "C" void kernel_launch(void* const* d_in, const int* in_sizes, int n_in,
                              void* d_out, int out_size)
{
    const float* q  = (const float*)d_in[0];
    const float* k  = (const float*)d_in[1];
    const float* v  = (const float*)d_in[2];
    const float* Wq = (const float*)d_in[3];
    const float* Wk = (const float*)d_in[4];
    const float* Wv = (const float*)d_in[5];
    const float* Wo = (const float*)d_in[6];
    const float* bo = (const float*)d_in[7];

    const int S = in_sizes[0] / DMODEL;   // 4096

    float *pQ, *pK, *pV, *pAO, *pT1;
    cudaGetSymbolAddress((void**)&pQ,  g_Q);
    cudaGetSymbolAddress((void**)&pK,  g_K);
    cudaGetSymbolAddress((void**)&pV,  g_V);
    cudaGetSymbolAddress((void**)&pAO, g_AO);
    cudaGetSymbolAddress((void**)&pT1, g_T1);

    dim3 gp(DMODEL / 128, S / 128);   // (4, 32)
    dim3 blk(256);

    // Projections
    sgemm_kernel<<<gp, blk>>>(q, Wq, pQ, nullptr, S, DMODEL, DMODEL);
    sgemm_kernel<<<gp, blk>>>(k, Wk, pK, nullptr, S, DMODEL, DMODEL);
    sgemm_kernel<<<gp, blk>>>(v, Wv, pV, nullptr, S, DMODEL, DMODEL);

    // Attention
    dim3 ga(S / 64, NHEAD);           // (64, 8)
    attn_kernel<<<ga, blk>>>(pQ, pK, pV, pAO, S);

    // Output projection applied twice
    sgemm_kernel<<<gp, blk>>>(pAO, Wo, pT1, bo, S, DMODEL, DMODEL);
    sgemm_kernel<<<gp, blk>>>(pT1, Wo, (float*)d_out, bo, S, DMODEL, DMODEL);
}

// round 2
// speedup vs baseline: 1.4744x; 1.4744x over previous
#include <cuda_runtime.h>
#include <math.h>

#define DMODEL 512
#define NHEAD 8
#define HD 64
#define MAXS 4096

// Scratch (no allocations allowed) — __device__ globals.
__device__ float g_Q[MAXS * DMODEL];
__device__ float g_K[MAXS * DMODEL];
__device__ float g_V[MAXS * DMODEL];
__device__ float g_AO[MAXS * DMODEL];
__device__ float g_T1[MAXS * DMODEL];

__device__ __forceinline__ float dot4(float4 a, float4 b) {
    return a.x * b.x + a.y * b.y + a.z * b.z + a.w * b.w;
}
__device__ __forceinline__ void fma4(float4& c, float a, float4 b) {
    c.x += a * b.x; c.y += a * b.y; c.z += a * b.z; c.w += a * b.w;
}

// ============================================================================
// SGEMM: C[M,N] = A[M,K] @ B[K,N] (+ bias per output column, optional)
// BM=128, BN=128, BK=16, 256 threads, 8x8 per thread (2x2 quadrants of 4x4)
// ============================================================================
__global__ __launch_bounds__(256) void sgemm_kernel(
    const float* __restrict__ A, const float* __restrict__ B,
    float* __restrict__ C, const float* __restrict__ bias,
    int M, int N, int K)
{
    __shared__ float As[16 * 132];  // transposed A tile, padded stride
    __shared__ float Bs[16 * 132];

    const int tid = threadIdx.x;
    const int tx = tid & 15, ty = tid >> 4;
    const int bm = blockIdx.y << 7, bn = blockIdx.x << 7;

    float4 acc[8][2];
#pragma unroll
    for (int i = 0; i < 8; i++) {
        acc[i][0] = make_float4(0.f, 0.f, 0.f, 0.f);
        acc[i][1] = make_float4(0.f, 0.f, 0.f, 0.f);
    }

    for (int k0 = 0; k0 < K; k0 += 16) {
        // Load A tile (128 x 16), store transposed As[k][m]
#pragma unroll
        for (int f = tid; f < 512; f += 256) {
            int r = f >> 2, c4 = (f & 3) << 2;
            float4 v = *(const float4*)(A + (size_t)(bm + r) * K + k0 + c4);
            As[(c4 + 0) * 132 + r] = v.x;
            As[(c4 + 1) * 132 + r] = v.y;
            As[(c4 + 2) * 132 + r] = v.z;
            As[(c4 + 3) * 132 + r] = v.w;
        }
        // Load B tile (16 x 128)
#pragma unroll
        for (int f = tid; f < 512; f += 256) {
            int r = f >> 5, c4 = (f & 31) << 2;
            *(float4*)(Bs + r * 132 + c4) =
                *(const float4*)(B + (size_t)(k0 + r) * N + bn + c4);
        }
        __syncthreads();

#pragma unroll
        for (int k = 0; k < 16; k++) {
            float4 aL = *(const float4*)(As + k * 132 + (ty << 2));
            float4 aH = *(const float4*)(As + k * 132 + 64 + (ty << 2));
            float4 bL = *(const float4*)(Bs + k * 132 + (tx << 2));
            float4 bH = *(const float4*)(Bs + k * 132 + 64 + (tx << 2));
            float av[8] = { aL.x, aL.y, aL.z, aL.w, aH.x, aH.y, aH.z, aH.w };
#pragma unroll
            for (int i = 0; i < 8; i++) {
                fma4(acc[i][0], av[i], bL);
                fma4(acc[i][1], av[i], bH);
            }
        }
        __syncthreads();
    }

    // Epilogue
#pragma unroll
    for (int i = 0; i < 8; i++) {
        int rloc = (i < 4) ? ((ty << 2) + i) : (64 + (ty << 2) + i - 4);
        int r = bm + rloc;
#pragma unroll
        for (int jq = 0; jq < 2; jq++) {
            int c = bn + (jq << 6) + (tx << 2);
            float4 v = acc[i][jq];
            if (bias) {
                v.x += bias[c + 0];
                v.y += bias[c + 1];
                v.z += bias[c + 2];
                v.w += bias[c + 3];
            }
            *(float4*)(C + (size_t)r * N + c) = v;
        }
    }
}

// ============================================================================
// Fused flash attention: per block, one head x 64 queries; loop over key tiles
// of 64. 256 threads (16x16), 4x4 S-tile per thread, online softmax.
// Smem: Qs / KPs (K tile, reused for P) / Vs = 3 x 16KB = 48KB exactly.
// XOR chunk swizzle + column mapping c = tx + 16j keeps every inner-loop
// LDS.128 at the minimal 2 phases (no bank conflicts).
// ============================================================================
__global__ __launch_bounds__(256, 2) void attn_kernel(
    const float* __restrict__ Q, const float* __restrict__ K,
    const float* __restrict__ V, float* __restrict__ O, int S)
{
    __shared__ float Qs[64 * 64];
    __shared__ float KPs[64 * 64];
    __shared__ float Vs[64 * 64];

    const int tid = threadIdx.x;
    const int tx = tid & 15, ty = tid >> 4;
    const int head = blockIdx.y;
    const int q0 = blockIdx.x << 6;

    // Load Q tile, pre-scaled by 1/sqrt(DK) = 1/8
    const float* Qg = Q + (size_t)q0 * DMODEL + head * HD;
#pragma unroll
    for (int f = tid; f < 1024; f += 256) {
        int r = f >> 4, c4 = f & 15;
        float4 v = *(const float4*)(Qg + (size_t)r * DMODEL + (c4 << 2));
        v.x *= 0.125f; v.y *= 0.125f; v.z *= 0.125f; v.w *= 0.125f;
        *(float4*)(Qs + (r << 6) + (((c4 ^ (r & 15))) << 2)) = v;
    }

    float m[4], l[4];
    float4 accv[4];
#pragma unroll
    for (int i = 0; i < 4; i++) {
        m[i] = -1e30f; l[i] = 0.f;
        accv[i] = make_float4(0.f, 0.f, 0.f, 0.f);
    }

    const int nkb = S >> 6;
    for (int kb = 0; kb < nkb; kb++) {
        const float* Kg = K + (size_t)(kb << 6) * DMODEL + head * HD;
        const float* Vg = V + (size_t)(kb << 6) * DMODEL + head * HD;
        __syncthreads();   // previous iteration fully done with KPs/Vs
#pragma unroll
        for (int f = tid; f < 1024; f += 256) {
            int r = f >> 4, c4 = f & 15;
            int off = (r << 6) + (((c4 ^ (r & 15))) << 2);
            *(float4*)(KPs + off) = *(const float4*)(Kg + (size_t)r * DMODEL + (c4 << 2));
            *(float4*)(Vs + off)  = *(const float4*)(Vg + (size_t)r * DMODEL + (c4 << 2));
        }
        __syncthreads();

        // S = Qtile @ Ktile^T  (64x64, 4x4 per thread)
        // Thread (tx,ty) owns rows 4*ty+i, columns tx + 16*j.
        // Key-fragment loads: row c = tx+16j, chunk d4 ^ (c&15) = d4 ^ tx
        // -> 16 lanes spread across all 8 bank groups (2-phase LDS.128).
        float s[4][4];
#pragma unroll
        for (int i = 0; i < 4; i++)
#pragma unroll
            for (int j = 0; j < 4; j++) s[i][j] = 0.f;

#pragma unroll
        for (int d4 = 0; d4 < 16; d4++) {
            float4 a[4], b[4];
#pragma unroll
            for (int i = 0; i < 4; i++) {
                int r = (ty << 2) + i;
                a[i] = *(const float4*)(Qs + (r << 6) + (((d4 ^ (r & 15))) << 2));
            }
#pragma unroll
            for (int j = 0; j < 4; j++) {
                int c = tx + (j << 4);
                b[j] = *(const float4*)(KPs + (c << 6) + (((d4 ^ (c & 15))) << 2));
            }
#pragma unroll
            for (int i = 0; i < 4; i++)
#pragma unroll
                for (int j = 0; j < 4; j++) s[i][j] += dot4(a[i], b[j]);
        }

        // Online softmax update. Row owned by the 16 threads with same ty:
        // lanes (ty&1)*16 + tx, so xor 1/2/4/8 stays in-group.
#pragma unroll
        for (int i = 0; i < 4; i++) {
            float bm = fmaxf(fmaxf(s[i][0], s[i][1]), fmaxf(s[i][2], s[i][3]));
#pragma unroll
            for (int o = 1; o < 16; o <<= 1)
                bm = fmaxf(bm, __shfl_xor_sync(0xffffffffu, bm, o));
            float mnew = fmaxf(m[i], bm);
            float alpha = __expf(m[i] - mnew);
            float sum = 0.f;
#pragma unroll
            for (int j = 0; j < 4; j++) {
                s[i][j] = __expf(s[i][j] - mnew);
                sum += s[i][j];
            }
#pragma unroll
            for (int o = 1; o < 16; o <<= 1)
                sum += __shfl_xor_sync(0xffffffffu, sum, o);
            l[i] = l[i] * alpha + sum;
            m[i] = mnew;
            accv[i].x *= alpha; accv[i].y *= alpha;
            accv[i].z *= alpha; accv[i].w *= alpha;
        }

        __syncthreads();   // everyone finished reading K from KPs
        // Store P into KPs (scalar, swizzle-consistent with pa loads below).
        // Banks: 4r + c spreads all 32 lanes -> conflict-free STS.32.
#pragma unroll
        for (int i = 0; i < 4; i++) {
            int r = (ty << 2) + i;
#pragma unroll
            for (int j = 0; j < 4; j++) {
                int c = tx + (j << 4);
                KPs[(r << 6) + ((((c >> 2) ^ (r & 15))) << 2) + (c & 3)] = s[i][j];
            }
        }
        __syncthreads();

        // O += P @ Vtile   (64x64 x 64x64)
#pragma unroll
        for (int k4 = 0; k4 < 16; k4++) {
            float4 pa[4], vb[4];
#pragma unroll
            for (int i = 0; i < 4; i++) {
                int r = (ty << 2) + i;
                pa[i] = *(const float4*)(KPs + (r << 6) + (((k4 ^ (r & 15))) << 2));
            }
#pragma unroll
            for (int kk = 0; kk < 4; kk++) {
                int kr = (k4 << 2) + kk;
                vb[kk] = *(const float4*)(Vs + (kr << 6) + (((tx ^ (kr & 15))) << 2));
            }
#pragma unroll
            for (int i = 0; i < 4; i++) {
                fma4(accv[i], pa[i].x, vb[0]);
                fma4(accv[i], pa[i].y, vb[1]);
                fma4(accv[i], pa[i].z, vb[2]);
                fma4(accv[i], pa[i].w, vb[3]);
            }
        }
    }

    // Epilogue: normalize and write [q0+r, head*64 + tx*4 ..]
    float* Og = O + (size_t)q0 * DMODEL + head * HD;
#pragma unroll
    for (int i = 0; i < 4; i++) {
        int r = (ty << 2) + i;
        float inv = 1.0f / l[i];
        float4 v = make_float4(accv[i].x * inv, accv[i].y * inv,
                               accv[i].z * inv, accv[i].w * inv);
        *(float4*)(Og + (size_t)r * DMODEL + (tx << 2)) = v;
    }
}

// ============================================================================
// kernel_launch
// ============================================================================
extern "C" void kernel_launch(void* const* d_in, const int* in_sizes, int n_in,
                              void* d_out, int out_size)
{
    const float* q  = (const float*)d_in[0];
    const float* k  = (const float*)d_in[1];
    const float* v  = (const float*)d_in[2];
    const float* Wq = (const float*)d_in[3];
    const float* Wk = (const float*)d_in[4];
    const float* Wv = (const float*)d_in[5];
    const float* Wo = (const float*)d_in[6];
    const float* bo = (const float*)d_in[7];

    const int S = in_sizes[0] / DMODEL;   // 4096

    float *pQ, *pK, *pV, *pAO, *pT1;
    cudaGetSymbolAddress((void**)&pQ,  g_Q);
    cudaGetSymbolAddress((void**)&pK,  g_K);
    cudaGetSymbolAddress((void**)&pV,  g_V);
    cudaGetSymbolAddress((void**)&pAO, g_AO);
    cudaGetSymbolAddress((void**)&pT1, g_T1);

    dim3 gp(DMODEL / 128, S / 128);   // (4, 32)
    dim3 blk(256);

    // Projections
    sgemm_kernel<<<gp, blk>>>(q, Wq, pQ, nullptr, S, DMODEL, DMODEL);
    sgemm_kernel<<<gp, blk>>>(k, Wk, pK, nullptr, S, DMODEL, DMODEL);
    sgemm_kernel<<<gp, blk>>>(v, Wv, pV, nullptr, S, DMODEL, DMODEL);

    // Attention
    dim3 ga(S / 64, NHEAD);           // (64, 8)
    attn_kernel<<<ga, blk>>>(pQ, pK, pV, pAO, S);

    // Output projection applied twice
    sgemm_kernel<<<gp, blk>>>(pAO, Wo, pT1, bo, S, DMODEL, DMODEL);
    sgemm_kernel<<<gp, blk>>>(pT1, Wo, (float*)d_out, bo, S, DMODEL, DMODEL);
}

// round 3
// speedup vs baseline: 2.8070x; 1.9038x over previous
#include <cuda_runtime.h>
#include <math.h>
#include <stdint.h>

#define DMODEL 512
#define NHEAD 8
#define HD 64
#define MAXS 4096

// Scratch (no allocations allowed) — __device__ globals.
__device__ float g_Q[MAXS * DMODEL];
__device__ float g_K[MAXS * DMODEL];
__device__ float g_V[MAXS * DMODEL];
__device__ float g_AO[MAXS * DMODEL];
__device__ float g_T1[MAXS * DMODEL];

__device__ __forceinline__ void fma4(float4& c, float a, float4 b) {
    c.x += a * b.x; c.y += a * b.y; c.z += a * b.z; c.w += a * b.w;
}

__device__ __forceinline__ uint32_t f2tf(float f) {
    uint32_t u;
    asm("cvt.rna.tf32.f32 %0, %1;" : "=r"(u) : "f"(f));
    return u;
}

__device__ __forceinline__ void mma_tf32(float* c, const uint32_t* a,
                                         uint32_t b0, uint32_t b1) {
    asm volatile(
        "mma.sync.aligned.m16n8k8.row.col.f32.tf32.tf32.f32 "
        "{%0,%1,%2,%3}, {%4,%5,%6,%7}, {%8,%9}, {%0,%1,%2,%3};\n"
        : "+f"(c[0]), "+f"(c[1]), "+f"(c[2]), "+f"(c[3])
        : "r"(a[0]), "r"(a[1]), "r"(a[2]), "r"(a[3]), "r"(b0), "r"(b1));
}

// ============================================================================
// SGEMM: C[M,N] = A[M,K] @ B[K,N] (+ bias), fp32 SIMT (unchanged this round)
// ============================================================================
__global__ __launch_bounds__(256) void sgemm_kernel(
    const float* __restrict__ A, const float* __restrict__ B,
    float* __restrict__ C, const float* __restrict__ bias,
    int M, int N, int K)
{
    __shared__ float As[16 * 132];
    __shared__ float Bs[16 * 132];

    const int tid = threadIdx.x;
    const int tx = tid & 15, ty = tid >> 4;
    const int bm = blockIdx.y << 7, bn = blockIdx.x << 7;

    float4 acc[8][2];
#pragma unroll
    for (int i = 0; i < 8; i++) {
        acc[i][0] = make_float4(0.f, 0.f, 0.f, 0.f);
        acc[i][1] = make_float4(0.f, 0.f, 0.f, 0.f);
    }

    for (int k0 = 0; k0 < K; k0 += 16) {
#pragma unroll
        for (int f = tid; f < 512; f += 256) {
            int r = f >> 2, c4 = (f & 3) << 2;
            float4 v = *(const float4*)(A + (size_t)(bm + r) * K + k0 + c4);
            As[(c4 + 0) * 132 + r] = v.x;
            As[(c4 + 1) * 132 + r] = v.y;
            As[(c4 + 2) * 132 + r] = v.z;
            As[(c4 + 3) * 132 + r] = v.w;
        }
#pragma unroll
        for (int f = tid; f < 512; f += 256) {
            int r = f >> 5, c4 = (f & 31) << 2;
            *(float4*)(Bs + r * 132 + c4) =
                *(const float4*)(B + (size_t)(k0 + r) * N + bn + c4);
        }
        __syncthreads();

#pragma unroll
        for (int k = 0; k < 16; k++) {
            float4 aL = *(const float4*)(As + k * 132 + (ty << 2));
            float4 aH = *(const float4*)(As + k * 132 + 64 + (ty << 2));
            float4 bL = *(const float4*)(Bs + k * 132 + (tx << 2));
            float4 bH = *(const float4*)(Bs + k * 132 + 64 + (tx << 2));
            float av[8] = { aL.x, aL.y, aL.z, aL.w, aH.x, aH.y, aH.z, aH.w };
#pragma unroll
            for (int i = 0; i < 8; i++) {
                fma4(acc[i][0], av[i], bL);
                fma4(acc[i][1], av[i], bH);
            }
        }
        __syncthreads();
    }

#pragma unroll
    for (int i = 0; i < 8; i++) {
        int rloc = (i < 4) ? ((ty << 2) + i) : (64 + (ty << 2) + i - 4);
        int r = bm + rloc;
#pragma unroll
        for (int jq = 0; jq < 2; jq++) {
            int c = bn + (jq << 6) + (tx << 2);
            float4 v = acc[i][jq];
            if (bias) {
                v.x += bias[c + 0];
                v.y += bias[c + 1];
                v.z += bias[c + 2];
                v.w += bias[c + 3];
            }
            *(float4*)(C + (size_t)r * N + c) = v;
        }
    }
}

// ============================================================================
// Flash attention with tf32 mma.sync (HMMA).
// Block: 128 threads = 4 warps; 64 q-rows per block (16 per warp), kv tiles
// of 64. Q held in registers as A-frags for the whole kv loop. K/V staged in
// smem (tf32, XOR chunk swizzle). P routed through a per-warp swizzled smem
// strip to form A-frags for PV. Online softmax in fp32 registers.
// Smem: Ks 16KB + Vs 16KB + Ps 16KB = 48KB.
// ============================================================================
__global__ __launch_bounds__(128, 3) void attn_tc_kernel(
    const float* __restrict__ Q, const float* __restrict__ K,
    const float* __restrict__ V, float* __restrict__ O, int S)
{
    __shared__ uint32_t Ks[64 * 64];
    __shared__ uint32_t Vs[64 * 64];
    __shared__ uint32_t Ps[4 * 16 * 64];

    const int tid = threadIdx.x;
    const int w = tid >> 5, lane = tid & 31;
    const int g = lane >> 2, q = lane & 3;       // group (row) / quad-pos (col)
    const int head = blockIdx.y;
    const int q0 = blockIdx.x << 6;
    const int rowA = q0 + (w << 4) + g;          // rows rowA, rowA+8

    // ---- Load Q fragments (scaled by 1/8, tf32) — once per block ----
    uint32_t aq[8][4];
    {
        const float* Q0 = Q + (size_t)rowA * DMODEL + head * HD;
        const float* Q1 = Q + (size_t)(rowA + 8) * DMODEL + head * HD;
#pragma unroll
        for (int kk = 0; kk < 8; kk++) {
            aq[kk][0] = f2tf(Q0[8 * kk + q] * 0.125f);
            aq[kk][1] = f2tf(Q1[8 * kk + q] * 0.125f);
            aq[kk][2] = f2tf(Q0[8 * kk + q + 4] * 0.125f);
            aq[kk][3] = f2tf(Q1[8 * kk + q + 4] * 0.125f);
        }
    }

    float o[8][4];
#pragma unroll
    for (int t = 0; t < 8; t++)
#pragma unroll
        for (int i = 0; i < 4; i++) o[t][i] = 0.f;
    float m0 = -1e30f, m1 = -1e30f, l0 = 0.f, l1 = 0.f;

    uint32_t* Pw = Ps + (w << 10);   // per-warp 16x64 strip

    const int nkb = S >> 6;
    for (int kb = 0; kb < nkb; kb++) {
        __syncthreads();   // all warps done reading previous K/V
        // ---- Stage K/V tile into smem (tf32, swizzled) ----
        {
            const float* Kg = K + (size_t)(kb << 6) * DMODEL + head * HD;
            const float* Vg = V + (size_t)(kb << 6) * DMODEL + head * HD;
#pragma unroll
            for (int f = tid; f < 1024; f += 128) {
                int r = f >> 4, c4 = f & 15;
                int off = (r << 6) + ((c4 ^ (r & 15)) << 2);
                float4 kv = *(const float4*)(Kg + (size_t)r * DMODEL + (c4 << 2));
                Ks[off + 0] = f2tf(kv.x); Ks[off + 1] = f2tf(kv.y);
                Ks[off + 2] = f2tf(kv.z); Ks[off + 3] = f2tf(kv.w);
                float4 vv = *(const float4*)(Vg + (size_t)r * DMODEL + (c4 << 2));
                Vs[off + 0] = f2tf(vv.x); Vs[off + 1] = f2tf(vv.y);
                Vs[off + 2] = f2tf(vv.z); Vs[off + 3] = f2tf(vv.w);
            }
        }
        __syncthreads();

        // ---- S = Q @ K^T : 8 n-tiles (8 cols each) x 8 k-steps ----
        float sc[8][4];
#pragma unroll
        for (int t = 0; t < 8; t++)
#pragma unroll
            for (int i = 0; i < 4; i++) sc[t][i] = 0.f;

#pragma unroll
        for (int kk = 0; kk < 8; kk++) {
#pragma unroll
            for (int t = 0; t < 8; t++) {
                int n = (t << 3) + g;          // key row
                int base = (n << 6);
                int nm = n & 15;
                uint32_t b0 = Ks[base + (((2 * kk) ^ nm) << 2) + q];
                uint32_t b1 = Ks[base + (((2 * kk + 1) ^ nm) << 2) + q];
                mma_tf32(sc[t], aq[kk], b0, b1);
            }
        }

        // ---- Online softmax (rows g -> sc[t][0..1], g+8 -> sc[t][2..3]) ----
        {
            float rm0 = -1e30f, rm1 = -1e30f;
#pragma unroll
            for (int t = 0; t < 8; t++) {
                rm0 = fmaxf(rm0, fmaxf(sc[t][0], sc[t][1]));
                rm1 = fmaxf(rm1, fmaxf(sc[t][2], sc[t][3]));
            }
            rm0 = fmaxf(rm0, __shfl_xor_sync(0xffffffffu, rm0, 1));
            rm0 = fmaxf(rm0, __shfl_xor_sync(0xffffffffu, rm0, 2));
            rm1 = fmaxf(rm1, __shfl_xor_sync(0xffffffffu, rm1, 1));
            rm1 = fmaxf(rm1, __shfl_xor_sync(0xffffffffu, rm1, 2));

            float mn0 = fmaxf(m0, rm0), mn1 = fmaxf(m1, rm1);
            float al0 = __expf(m0 - mn0), al1 = __expf(m1 - mn1);
            float s0 = 0.f, s1 = 0.f;
#pragma unroll
            for (int t = 0; t < 8; t++) {
                sc[t][0] = __expf(sc[t][0] - mn0);
                sc[t][1] = __expf(sc[t][1] - mn0);
                sc[t][2] = __expf(sc[t][2] - mn1);
                sc[t][3] = __expf(sc[t][3] - mn1);
                s0 += sc[t][0] + sc[t][1];
                s1 += sc[t][2] + sc[t][3];
            }
            s0 += __shfl_xor_sync(0xffffffffu, s0, 1);
            s0 += __shfl_xor_sync(0xffffffffu, s0, 2);
            s1 += __shfl_xor_sync(0xffffffffu, s1, 1);
            s1 += __shfl_xor_sync(0xffffffffu, s1, 2);
            l0 = l0 * al0 + s0;  m0 = mn0;
            l1 = l1 * al1 + s1;  m1 = mn1;
#pragma unroll
            for (int t = 0; t < 8; t++) {
                o[t][0] *= al0; o[t][1] *= al0;
                o[t][2] *= al1; o[t][3] *= al1;
            }
        }

        // ---- Store P to per-warp smem strip (tf32, swizzled) ----
#pragma unroll
        for (int t = 0; t < 8; t++) {
            int col = (t << 3) + (q << 1);             // 8t + 2q
            int ch = col >> 2, cl = col & 3;
            int a0 = (g << 6) + (((ch ^ (g & 15))) << 2) + cl;
            Pw[a0] = f2tf(sc[t][0]);  Pw[a0 + 1] = f2tf(sc[t][1]);
            int r1 = g + 8;
            int a1 = (r1 << 6) + (((ch ^ (r1 & 15))) << 2) + cl;
            Pw[a1] = f2tf(sc[t][2]);  Pw[a1 + 1] = f2tf(sc[t][3]);
        }
        __syncwarp();

        // ---- O += P @ V : 8 k-steps (kv) x 8 n-tiles (head dim) ----
#pragma unroll
        for (int kk = 0; kk < 8; kk++) {
            uint32_t ap[4];
            int r0 = g, r1 = g + 8;
            ap[0] = Pw[(r0 << 6) + (((2 * kk)     ^ (r0 & 15)) << 2) + q];
            ap[1] = Pw[(r1 << 6) + (((2 * kk)     ^ (r1 & 15)) << 2) + q];
            ap[2] = Pw[(r0 << 6) + (((2 * kk + 1) ^ (r0 & 15)) << 2) + q];
            ap[3] = Pw[(r1 << 6) + (((2 * kk + 1) ^ (r1 & 15)) << 2) + q];
#pragma unroll
            for (int t = 0; t < 8; t++) {
                int n = (t << 3) + g;                  // V column (head dim)
                int ch = n >> 2, cl = n & 3;
                int k0 = (kk << 3) + q, k1 = k0 + 4;   // V rows (kv dim)
                uint32_t b0 = Vs[(k0 << 6) + ((ch ^ (k0 & 15)) << 2) + cl];
                uint32_t b1 = Vs[(k1 << 6) + ((ch ^ (k1 & 15)) << 2) + cl];
                mma_tf32(o[t], ap, b0, b1);
            }
        }
    }

    // ---- Epilogue: normalize, write O ----
    {
        float inv0 = 1.0f / l0, inv1 = 1.0f / l1;
        float* O0 = O + (size_t)rowA * DMODEL + head * HD;
        float* O1 = O + (size_t)(rowA + 8) * DMODEL + head * HD;
#pragma unroll
        for (int t = 0; t < 8; t++) {
            int col = (t << 3) + (q << 1);
            *(float2*)(O0 + col) = make_float2(o[t][0] * inv0, o[t][1] * inv0);
            *(float2*)(O1 + col) = make_float2(o[t][2] * inv1, o[t][3] * inv1);
        }
    }
}

// ============================================================================
// kernel_launch
// ============================================================================
extern "C" void kernel_launch(void* const* d_in, const int* in_sizes, int n_in,
                              void* d_out, int out_size)
{
    const float* q  = (const float*)d_in[0];
    const float* k  = (const float*)d_in[1];
    const float* v  = (const float*)d_in[2];
    const float* Wq = (const float*)d_in[3];
    const float* Wk = (const float*)d_in[4];
    const float* Wv = (const float*)d_in[5];
    const float* Wo = (const float*)d_in[6];
    const float* bo = (const float*)d_in[7];

    const int S = in_sizes[0] / DMODEL;   // 4096

    float *pQ, *pK, *pV, *pAO, *pT1;
    cudaGetSymbolAddress((void**)&pQ,  g_Q);
    cudaGetSymbolAddress((void**)&pK,  g_K);
    cudaGetSymbolAddress((void**)&pV,  g_V);
    cudaGetSymbolAddress((void**)&pAO, g_AO);
    cudaGetSymbolAddress((void**)&pT1, g_T1);

    dim3 gp(DMODEL / 128, S / 128);   // (4, 32)
    dim3 blk(256);

    // Projections
    sgemm_kernel<<<gp, blk>>>(q, Wq, pQ, nullptr, S, DMODEL, DMODEL);
    sgemm_kernel<<<gp, blk>>>(k, Wk, pK, nullptr, S, DMODEL, DMODEL);
    sgemm_kernel<<<gp, blk>>>(v, Wv, pV, nullptr, S, DMODEL, DMODEL);

    // Attention (tf32 tensor cores)
    dim3 ga(S / 64, NHEAD);           // (64, 8)
    attn_tc_kernel<<<ga, dim3(128)>>>(pQ, pK, pV, pAO, S);

    // Output projection applied twice
    sgemm_kernel<<<gp, blk>>>(pAO, Wo, pT1, bo, S, DMODEL, DMODEL);
    sgemm_kernel<<<gp, blk>>>(pT1, Wo, (float*)d_out, bo, S, DMODEL, DMODEL);
}

// round 4
// speedup vs baseline: 3.2588x; 1.1609x over previous
#include <cuda_runtime.h>
#include <math.h>
#include <stdint.h>

#define DMODEL 512
#define NHEAD 8
#define HD 64
#define MAXS 4096

// Scratch (no allocations allowed) — __device__ globals.
__device__ float g_Q[MAXS * DMODEL];
__device__ float g_K[MAXS * DMODEL];
__device__ float g_V[MAXS * DMODEL];
__device__ float g_AO[MAXS * DMODEL];
__device__ float g_T1[MAXS * DMODEL];

__device__ __forceinline__ uint32_t f2tf(float f) {
    uint32_t u;
    asm("cvt.rna.tf32.f32 %0, %1;" : "=r"(u) : "f"(f));
    return u;
}

__device__ __forceinline__ void mma_tf32(float* c, const uint32_t* a,
                                         uint32_t b0, uint32_t b1) {
    asm volatile(
        "mma.sync.aligned.m16n8k8.row.col.f32.tf32.tf32.f32 "
        "{%0,%1,%2,%3}, {%4,%5,%6,%7}, {%8,%9}, {%0,%1,%2,%3};\n"
        : "+f"(c[0]), "+f"(c[1]), "+f"(c[2]), "+f"(c[3])
        : "r"(a[0]), "r"(a[1]), "r"(a[2]), "r"(a[3]), "r"(b0), "r"(b1));
}

__device__ __forceinline__ void ldsm_x4(uint32_t& r0, uint32_t& r1,
                                        uint32_t& r2, uint32_t& r3,
                                        uint32_t addr) {
    asm volatile("ldmatrix.sync.aligned.m8n8.x4.shared.b16 {%0,%1,%2,%3}, [%4];"
                 : "=r"(r0), "=r"(r1), "=r"(r2), "=r"(r3) : "r"(addr));
}

__device__ __forceinline__ uint32_t s2u(const void* p) {
    return (uint32_t)__cvta_generic_to_shared(p);
}

// ============================================================================
// tf32 tensor-core GEMM: C[M,N] = A[M,K] @ B[K,N] (+ bias).
// 256 threads = 8 warps (4m x 2n), block tile 128x128, BK=16.
// A staged in smem (tf32, XOR chunk swizzle conflict-free for STS.128 and
// ldmatrix.x4). B fragments loaded directly from gmem/L2 (coalesced sectors).
// ============================================================================
__global__ __launch_bounds__(256, 2) void gemm_tc_kernel(
    const float* __restrict__ A, const float* __restrict__ B,
    float* __restrict__ C, const float* __restrict__ bias,
    int M, int N, int K)
{
    __shared__ uint32_t As[128 * 16];   // [r][16 words], chunk c at c^((r>>1)&3)

    const int tid = threadIdx.x;
    const int w = tid >> 5, lane = tid & 31;
    const int g = lane >> 2, q = lane & 3;
    const int wm = w >> 1, wn = w & 1;
    const int bm = blockIdx.y << 7, bn = blockIdx.x << 7;
    const int n0 = bn + (wn << 6);

    float acc[2][8][4];
#pragma unroll
    for (int mb = 0; mb < 2; mb++)
#pragma unroll
        for (int t = 0; t < 8; t++)
#pragma unroll
            for (int i = 0; i < 4; i++) acc[mb][t][i] = 0.f;

    const uint32_t asb = s2u(As);
    // ldmatrix lane-constant pieces: tile tp = lane>>3
    const int tp = lane >> 3;
    const int arow_l = ((tp & 1) << 3) + (lane & 7);          // 0..15
    const int asw = (arow_l >> 1) & 3;                         // swizzle bits

    for (int k0 = 0; k0 < K; k0 += 16) {
        __syncthreads();
        // ---- stage A tile (128x16) as tf32, swizzled ----
#pragma unroll
        for (int p = 0; p < 2; p++) {
            int f = tid + (p << 8);
            int r = f >> 2, c = f & 3;
            float4 v = *(const float4*)(A + (size_t)(bm + r) * K + k0 + (c << 2));
            uint32_t* dst = &As[(r << 4) + ((c ^ ((r >> 1) & 3)) << 2)];
            uint4 u = make_uint4(f2tf(v.x), f2tf(v.y), f2tf(v.z), f2tf(v.w));
            *(uint4*)dst = u;
        }
        __syncthreads();

#pragma unroll
        for (int ks = 0; ks < 2; ks++) {
            const int krow = k0 + (ks << 3);
            // ---- B fragments straight from gmem (L2-resident) ----
            uint32_t bf[8][2];
#pragma unroll
            for (int t = 0; t < 8; t++) {
                const float* bp = B + (size_t)(krow + q) * N + n0 + (t << 3) + g;
                bf[t][0] = f2tf(__ldg(bp));
                bf[t][1] = f2tf(__ldg(bp + 4 * N));
            }
            // ---- A fragments via ldmatrix.x4 ----
            uint32_t a[2][4];
#pragma unroll
            for (int mb = 0; mb < 2; mb++) {
                int r = (wm << 5) + (mb << 4) + arow_l;
                int ch = (ks << 1) + (tp >> 1);
                uint32_t addr = asb + (((r << 4) + ((ch ^ asw) << 2)) << 2);
                ldsm_x4(a[mb][0], a[mb][1], a[mb][2], a[mb][3], addr);
            }
#pragma unroll
            for (int mb = 0; mb < 2; mb++)
#pragma unroll
                for (int t = 0; t < 8; t++)
                    mma_tf32(acc[mb][t], a[mb], bf[t][0], bf[t][1]);
        }
    }

    // ---- epilogue ----
#pragma unroll
    for (int mb = 0; mb < 2; mb++) {
        int row = bm + (wm << 5) + (mb << 4) + g;
#pragma unroll
        for (int t = 0; t < 8; t++) {
            int col = n0 + (t << 3) + (q << 1);
            float b0 = 0.f, b1 = 0.f;
            if (bias) { b0 = bias[col]; b1 = bias[col + 1]; }
            *(float2*)(C + (size_t)row * N + col) =
                make_float2(acc[mb][t][0] + b0, acc[mb][t][1] + b1);
            *(float2*)(C + (size_t)(row + 8) * N + col) =
                make_float2(acc[mb][t][2] + b0, acc[mb][t][3] + b1);
        }
    }
}

// ============================================================================
// Flash attention, tf32 mma + ldmatrix fragment loads.
// 4 warps, 64 q-rows/block (16/warp), kv tiles of 64. Q frags in regs.
// QK B-frags and P A-frags via ldmatrix.x4; PV B scalar LDS (conflict-free).
// ============================================================================
__global__ __launch_bounds__(128, 3) void attn_tc_kernel(
    const float* __restrict__ Q, const float* __restrict__ K,
    const float* __restrict__ V, float* __restrict__ O, int S)
{
    __shared__ uint32_t Ks[64 * 64];
    __shared__ uint32_t Vs[64 * 64];
    __shared__ uint32_t Ps[4 * 16 * 64];

    const int tid = threadIdx.x;
    const int w = tid >> 5, lane = tid & 31;
    const int g = lane >> 2, q = lane & 3;
    const int head = blockIdx.y;
    const int q0 = blockIdx.x << 6;
    const int rowA = q0 + (w << 4) + g;

    // ldmatrix lane-constant addressing pieces
    const int tp = lane >> 3;
    // QK B tiles: rows 8*(t + tp>>1) + (lane&7), chunk 2kk + (tp&1)
    const int kb_row = ((tp >> 1) << 3) + (lane & 7);   // 0..15 (t adds 16s)
    // P A tiles: rows (tp&1)*8 + (lane&7), chunk 2kk + (tp>>1)
    const int pa_row = ((tp & 1) << 3) + (lane & 7);    // 0..15

    const uint32_t ksb = s2u(Ks);
    const uint32_t pwb = s2u(Ps) + (w << 12);           // w*1024 words*4B

    // ---- Load Q fragments (scaled by 1/8, tf32) ----
    uint32_t aq[8][4];
    {
        const float* Q0 = Q + (size_t)rowA * DMODEL + head * HD;
        const float* Q1 = Q + (size_t)(rowA + 8) * DMODEL + head * HD;
#pragma unroll
        for (int kk = 0; kk < 8; kk++) {
            aq[kk][0] = f2tf(Q0[8 * kk + q] * 0.125f);
            aq[kk][1] = f2tf(Q1[8 * kk + q] * 0.125f);
            aq[kk][2] = f2tf(Q0[8 * kk + q + 4] * 0.125f);
            aq[kk][3] = f2tf(Q1[8 * kk + q + 4] * 0.125f);
        }
    }

    float o[8][4];
#pragma unroll
    for (int t = 0; t < 8; t++)
#pragma unroll
        for (int i = 0; i < 4; i++) o[t][i] = 0.f;
    float m0 = -1e30f, m1 = -1e30f, l0 = 0.f, l1 = 0.f;

    uint32_t* Pw = Ps + (w << 10);

    const int nkb = S >> 6;
    for (int kb = 0; kb < nkb; kb++) {
        __syncthreads();
        // ---- Stage K/V tile (tf32, XOR chunk swizzle) ----
        {
            const float* Kg = K + (size_t)(kb << 6) * DMODEL + head * HD;
            const float* Vg = V + (size_t)(kb << 6) * DMODEL + head * HD;
#pragma unroll
            for (int f = tid; f < 1024; f += 128) {
                int r = f >> 4, c4 = f & 15;
                int off = (r << 6) + ((c4 ^ (r & 15)) << 2);
                float4 kv = *(const float4*)(Kg + (size_t)r * DMODEL + (c4 << 2));
                Ks[off + 0] = f2tf(kv.x); Ks[off + 1] = f2tf(kv.y);
                Ks[off + 2] = f2tf(kv.z); Ks[off + 3] = f2tf(kv.w);
                float4 vv = *(const float4*)(Vg + (size_t)r * DMODEL + (c4 << 2));
                Vs[off + 0] = f2tf(vv.x); Vs[off + 1] = f2tf(vv.y);
                Vs[off + 2] = f2tf(vv.z); Vs[off + 3] = f2tf(vv.w);
            }
        }
        __syncthreads();

        // ---- S = Q @ K^T (B-frags via ldmatrix.x4) ----
        float sc[8][4];
#pragma unroll
        for (int t = 0; t < 8; t++)
#pragma unroll
            for (int i = 0; i < 4; i++) sc[t][i] = 0.f;

#pragma unroll
        for (int kk = 0; kk < 8; kk++) {
            const int ch = (kk << 1) + (tp & 1);
#pragma unroll
            for (int th = 0; th < 4; th++) {
                int row = (th << 4) + kb_row;          // keys 16*th + ...
                uint32_t addr = ksb + (((row << 6) + ((ch ^ (row & 15)) << 2)) << 2);
                uint32_t b0, b1, b2, b3;
                ldsm_x4(b0, b1, b2, b3, addr);
                mma_tf32(sc[2 * th + 0], aq[kk], b0, b1);
                mma_tf32(sc[2 * th + 1], aq[kk], b2, b3);
            }
        }

        // ---- Online softmax ----
        {
            float rm0 = -1e30f, rm1 = -1e30f;
#pragma unroll
            for (int t = 0; t < 8; t++) {
                rm0 = fmaxf(rm0, fmaxf(sc[t][0], sc[t][1]));
                rm1 = fmaxf(rm1, fmaxf(sc[t][2], sc[t][3]));
            }
            rm0 = fmaxf(rm0, __shfl_xor_sync(0xffffffffu, rm0, 1));
            rm0 = fmaxf(rm0, __shfl_xor_sync(0xffffffffu, rm0, 2));
            rm1 = fmaxf(rm1, __shfl_xor_sync(0xffffffffu, rm1, 1));
            rm1 = fmaxf(rm1, __shfl_xor_sync(0xffffffffu, rm1, 2));

            float mn0 = fmaxf(m0, rm0), mn1 = fmaxf(m1, rm1);
            float al0 = __expf(m0 - mn0), al1 = __expf(m1 - mn1);
            float s0 = 0.f, s1 = 0.f;
#pragma unroll
            for (int t = 0; t < 8; t++) {
                sc[t][0] = __expf(sc[t][0] - mn0);
                sc[t][1] = __expf(sc[t][1] - mn0);
                sc[t][2] = __expf(sc[t][2] - mn1);
                sc[t][3] = __expf(sc[t][3] - mn1);
                s0 += sc[t][0] + sc[t][1];
                s1 += sc[t][2] + sc[t][3];
            }
            s0 += __shfl_xor_sync(0xffffffffu, s0, 1);
            s0 += __shfl_xor_sync(0xffffffffu, s0, 2);
            s1 += __shfl_xor_sync(0xffffffffu, s1, 1);
            s1 += __shfl_xor_sync(0xffffffffu, s1, 2);
            l0 = l0 * al0 + s0;  m0 = mn0;
            l1 = l1 * al1 + s1;  m1 = mn1;
#pragma unroll
            for (int t = 0; t < 8; t++) {
                o[t][0] *= al0; o[t][1] *= al0;
                o[t][2] *= al1; o[t][3] *= al1;
            }
        }

        // ---- Store P (scalar STS, swizzled row-major [m][kv]) ----
#pragma unroll
        for (int t = 0; t < 8; t++) {
            int col = (t << 3) + (q << 1);
            int ch = col >> 2, cl = col & 3;
            int a0 = (g << 6) + ((ch ^ (g & 15)) << 2) + cl;
            Pw[a0] = f2tf(sc[t][0]);  Pw[a0 + 1] = f2tf(sc[t][1]);
            int r1 = g + 8;
            int a1 = (r1 << 6) + ((ch ^ (r1 & 15)) << 2) + cl;
            Pw[a1] = f2tf(sc[t][2]);  Pw[a1 + 1] = f2tf(sc[t][3]);
        }
        __syncwarp();

        // ---- O += P @ V (A-frags via ldmatrix.x4, B scalar LDS) ----
#pragma unroll
        for (int kk = 0; kk < 8; kk++) {
            uint32_t ap[4];
            {
                int ch = (kk << 1) + (tp >> 1);
                uint32_t addr = pwb +
                    (((pa_row << 6) + ((ch ^ (pa_row & 15)) << 2)) << 2);
                ldsm_x4(ap[0], ap[1], ap[2], ap[3], addr);
            }
#pragma unroll
            for (int t = 0; t < 8; t++) {
                int n = (t << 3) + g;
                int ch = n >> 2, cl = n & 3;
                int k0 = (kk << 3) + q, k1 = k0 + 4;
                uint32_t b0 = Vs[(k0 << 6) + ((ch ^ (k0 & 15)) << 2) + cl];
                uint32_t b1 = Vs[(k1 << 6) + ((ch ^ (k1 & 15)) << 2) + cl];
                mma_tf32(o[t], ap, b0, b1);
            }
        }
    }

    // ---- Epilogue ----
    {
        float inv0 = 1.0f / l0, inv1 = 1.0f / l1;
        float* O0 = O + (size_t)rowA * DMODEL + head * HD;
        float* O1 = O + (size_t)(rowA + 8) * DMODEL + head * HD;
#pragma unroll
        for (int t = 0; t < 8; t++) {
            int col = (t << 3) + (q << 1);
            *(float2*)(O0 + col) = make_float2(o[t][0] * inv0, o[t][1] * inv0);
            *(float2*)(O1 + col) = make_float2(o[t][2] * inv1, o[t][3] * inv1);
        }
    }
}

// ============================================================================
// kernel_launch
// ============================================================================
extern "C" void kernel_launch(void* const* d_in, const int* in_sizes, int n_in,
                              void* d_out, int out_size)
{
    const float* q  = (const float*)d_in[0];
    const float* k  = (const float*)d_in[1];
    const float* v  = (const float*)d_in[2];
    const float* Wq = (const float*)d_in[3];
    const float* Wk = (const float*)d_in[4];
    const float* Wv = (const float*)d_in[5];
    const float* Wo = (const float*)d_in[6];
    const float* bo = (const float*)d_in[7];

    const int S = in_sizes[0] / DMODEL;   // 4096

    float *pQ, *pK, *pV, *pAO, *pT1;
    cudaGetSymbolAddress((void**)&pQ,  g_Q);
    cudaGetSymbolAddress((void**)&pK,  g_K);
    cudaGetSymbolAddress((void**)&pV,  g_V);
    cudaGetSymbolAddress((void**)&pAO, g_AO);
    cudaGetSymbolAddress((void**)&pT1, g_T1);

    dim3 gp(DMODEL / 128, S / 128);   // (4, 32)
    dim3 blk(256);

    // Projections (tf32 tensor cores)
    gemm_tc_kernel<<<gp, blk>>>(q, Wq, pQ, nullptr, S, DMODEL, DMODEL);
    gemm_tc_kernel<<<gp, blk>>>(k, Wk, pK, nullptr, S, DMODEL, DMODEL);
    gemm_tc_kernel<<<gp, blk>>>(v, Wv, pV, nullptr, S, DMODEL, DMODEL);

    // Attention (tf32 tensor cores)
    dim3 ga(S / 64, NHEAD);           // (64, 8)
    attn_tc_kernel<<<ga, dim3(128)>>>(pQ, pK, pV, pAO, S);

    // Output projection applied twice (tf32 tensor cores)
    gemm_tc_kernel<<<gp, blk>>>(pAO, Wo, pT1, bo, S, DMODEL, DMODEL);
    gemm_tc_kernel<<<gp, blk>>>(pT1, Wo, (float*)d_out, bo, S, DMODEL, DMODEL);
}

// round 5
// speedup vs baseline: 4.1821x; 1.2833x over previous
#include <cuda_runtime.h>
#include <math.h>
#include <stdint.h>

#define DMODEL 512
#define NHEAD 8
#define HD 64
#define MAXS 4096

// Scratch (no allocations allowed) — __device__ globals.
__device__ float g_Q[MAXS * DMODEL];
__device__ float g_K[MAXS * DMODEL];
__device__ float g_V[MAXS * DMODEL];
__device__ float g_AO[MAXS * DMODEL];
__device__ float g_T1[MAXS * DMODEL];

__device__ __forceinline__ uint32_t f2tf(float f) {
    uint32_t u;
    asm("cvt.rna.tf32.f32 %0, %1;" : "=r"(u) : "f"(f));
    return u;
}

__device__ __forceinline__ void mma_tf32(float* c, const uint32_t* a,
                                         uint32_t b0, uint32_t b1) {
    asm volatile(
        "mma.sync.aligned.m16n8k8.row.col.f32.tf32.tf32.f32 "
        "{%0,%1,%2,%3}, {%4,%5,%6,%7}, {%8,%9}, {%0,%1,%2,%3};\n"
        : "+f"(c[0]), "+f"(c[1]), "+f"(c[2]), "+f"(c[3])
        : "r"(a[0]), "r"(a[1]), "r"(a[2]), "r"(a[3]), "r"(b0), "r"(b1));
}

__device__ __forceinline__ void ldsm_x4(uint32_t& r0, uint32_t& r1,
                                        uint32_t& r2, uint32_t& r3,
                                        uint32_t addr) {
    asm volatile("ldmatrix.sync.aligned.m8n8.x4.shared.b16 {%0,%1,%2,%3}, [%4];"
                 : "=r"(r0), "=r"(r1), "=r"(r2), "=r"(r3) : "r"(addr));
}

__device__ __forceinline__ uint32_t s2u(const void* p) {
    return (uint32_t)__cvta_generic_to_shared(p);
}

// ============================================================================
// tf32 tensor-core GEMM (unchanged from round 4).
// ============================================================================
__global__ __launch_bounds__(256, 2) void gemm_tc_kernel(
    const float* __restrict__ A, const float* __restrict__ B,
    float* __restrict__ C, const float* __restrict__ bias,
    int M, int N, int K)
{
    __shared__ uint32_t As[128 * 16];

    const int tid = threadIdx.x;
    const int w = tid >> 5, lane = tid & 31;
    const int g = lane >> 2, q = lane & 3;
    const int wm = w >> 1, wn = w & 1;
    const int bm = blockIdx.y << 7, bn = blockIdx.x << 7;
    const int n0 = bn + (wn << 6);

    float acc[2][8][4];
#pragma unroll
    for (int mb = 0; mb < 2; mb++)
#pragma unroll
        for (int t = 0; t < 8; t++)
#pragma unroll
            for (int i = 0; i < 4; i++) acc[mb][t][i] = 0.f;

    const uint32_t asb = s2u(As);
    const int tp = lane >> 3;
    const int arow_l = ((tp & 1) << 3) + (lane & 7);
    const int asw = (arow_l >> 1) & 3;

    for (int k0 = 0; k0 < K; k0 += 16) {
        __syncthreads();
#pragma unroll
        for (int p = 0; p < 2; p++) {
            int f = tid + (p << 8);
            int r = f >> 2, c = f & 3;
            float4 v = *(const float4*)(A + (size_t)(bm + r) * K + k0 + (c << 2));
            uint32_t* dst = &As[(r << 4) + ((c ^ ((r >> 1) & 3)) << 2)];
            uint4 u = make_uint4(f2tf(v.x), f2tf(v.y), f2tf(v.z), f2tf(v.w));
            *(uint4*)dst = u;
        }
        __syncthreads();

#pragma unroll
        for (int ks = 0; ks < 2; ks++) {
            const int krow = k0 + (ks << 3);
            uint32_t bf[8][2];
#pragma unroll
            for (int t = 0; t < 8; t++) {
                const float* bp = B + (size_t)(krow + q) * N + n0 + (t << 3) + g;
                bf[t][0] = f2tf(__ldg(bp));
                bf[t][1] = f2tf(__ldg(bp + 4 * N));
            }
            uint32_t a[2][4];
#pragma unroll
            for (int mb = 0; mb < 2; mb++) {
                int r = (wm << 5) + (mb << 4) + arow_l;
                int ch = (ks << 1) + (tp >> 1);
                uint32_t addr = asb + (((r << 4) + ((ch ^ asw) << 2)) << 2);
                ldsm_x4(a[mb][0], a[mb][1], a[mb][2], a[mb][3], addr);
            }
#pragma unroll
            for (int mb = 0; mb < 2; mb++)
#pragma unroll
                for (int t = 0; t < 8; t++)
                    mma_tf32(acc[mb][t], a[mb], bf[t][0], bf[t][1]);
        }
    }

#pragma unroll
    for (int mb = 0; mb < 2; mb++) {
        int row = bm + (wm << 5) + (mb << 4) + g;
#pragma unroll
        for (int t = 0; t < 8; t++) {
            int col = n0 + (t << 3) + (q << 1);
            float b0 = 0.f, b1 = 0.f;
            if (bias) { b0 = bias[col]; b1 = bias[col + 1]; }
            *(float2*)(C + (size_t)row * N + col) =
                make_float2(acc[mb][t][0] + b0, acc[mb][t][1] + b1);
            *(float2*)(C + (size_t)(row + 8) * N + col) =
                make_float2(acc[mb][t][2] + b0, acc[mb][t][3] + b1);
        }
    }
}

// ============================================================================
// Flash attention, tf32 mma, 32 q-rows per warp (two m16 tiles share every
// K/V fragment). 4 warps, 128 q-rows/block, kv tiles of 64.
// Dynamic smem 64KB: Ks 16KB | Vs 16KB | Ps 32KB (per-warp 32x64 strips).
// ============================================================================
__global__ __launch_bounds__(128, 2) void attn_tc_kernel(
    const float* __restrict__ Q, const float* __restrict__ K,
    const float* __restrict__ V, float* __restrict__ O, int S)
{
    extern __shared__ uint32_t sh[];
    uint32_t* Ks = sh;              // 64*64
    uint32_t* Vs = sh + 4096;       // 64*64
    uint32_t* Ps = sh + 8192;       // 4 * 32 * 64

    const int tid = threadIdx.x;
    const int w = tid >> 5, lane = tid & 31;
    const int g = lane >> 2, q = lane & 3;
    const int head = blockIdx.y;
    const int q0 = blockIdx.x << 7;
    const int rowW = q0 + (w << 5);           // warp's 32 rows

    const int tp = lane >> 3;
    const int kb_row = ((tp >> 1) << 3) + (lane & 7);   // QK B-tile rows
    const int pa_row = ((tp & 1) << 3) + (lane & 7);    // P A-tile rows

    const uint32_t ksb = s2u(Ks);
    const uint32_t pwb = s2u(Ps) + (w << 13);           // w * 2048 words * 4B
    uint32_t* Pw = Ps + (w << 11);

    // ---- Load Q fragments (scaled by 1/8, tf32): 2 m-tiles x 8 k-steps ----
    uint32_t aq[2][8][4];
#pragma unroll
    for (int mb = 0; mb < 2; mb++) {
        const float* Q0 = Q + (size_t)(rowW + (mb << 4) + g) * DMODEL + head * HD;
        const float* Q1 = Q0 + 8 * DMODEL;
#pragma unroll
        for (int kk = 0; kk < 8; kk++) {
            aq[mb][kk][0] = f2tf(Q0[8 * kk + q] * 0.125f);
            aq[mb][kk][1] = f2tf(Q1[8 * kk + q] * 0.125f);
            aq[mb][kk][2] = f2tf(Q0[8 * kk + q + 4] * 0.125f);
            aq[mb][kk][3] = f2tf(Q1[8 * kk + q + 4] * 0.125f);
        }
    }

    float o[2][8][4];
#pragma unroll
    for (int mb = 0; mb < 2; mb++)
#pragma unroll
        for (int t = 0; t < 8; t++)
#pragma unroll
            for (int i = 0; i < 4; i++) o[mb][t][i] = 0.f;
    float m0[2] = { -1e30f, -1e30f }, m1[2] = { -1e30f, -1e30f };
    float l0[2] = { 0.f, 0.f }, l1[2] = { 0.f, 0.f };

    const int nkb = S >> 6;
    for (int kb = 0; kb < nkb; kb++) {
        __syncthreads();
        // ---- Stage K/V tile (tf32, XOR chunk swizzle) ----
        {
            const float* Kg = K + (size_t)(kb << 6) * DMODEL + head * HD;
            const float* Vg = V + (size_t)(kb << 6) * DMODEL + head * HD;
#pragma unroll
            for (int f = tid; f < 1024; f += 128) {
                int r = f >> 4, c4 = f & 15;
                int off = (r << 6) + ((c4 ^ (r & 15)) << 2);
                float4 kv = *(const float4*)(Kg + (size_t)r * DMODEL + (c4 << 2));
                Ks[off + 0] = f2tf(kv.x); Ks[off + 1] = f2tf(kv.y);
                Ks[off + 2] = f2tf(kv.z); Ks[off + 3] = f2tf(kv.w);
                float4 vv = *(const float4*)(Vg + (size_t)r * DMODEL + (c4 << 2));
                Vs[off + 0] = f2tf(vv.x); Vs[off + 1] = f2tf(vv.y);
                Vs[off + 2] = f2tf(vv.z); Vs[off + 3] = f2tf(vv.w);
            }
        }
        __syncthreads();

        // ---- S = Q @ K^T : each K fragment feeds both m-tiles ----
        float sc[2][8][4];
#pragma unroll
        for (int mb = 0; mb < 2; mb++)
#pragma unroll
            for (int t = 0; t < 8; t++)
#pragma unroll
                for (int i = 0; i < 4; i++) sc[mb][t][i] = 0.f;

#pragma unroll
        for (int kk = 0; kk < 8; kk++) {
            const int ch = (kk << 1) + (tp & 1);
#pragma unroll
            for (int th = 0; th < 4; th++) {
                int row = (th << 4) + kb_row;
                uint32_t addr = ksb + (((row << 6) + ((ch ^ (row & 15)) << 2)) << 2);
                uint32_t b0, b1, b2, b3;
                ldsm_x4(b0, b1, b2, b3, addr);
                mma_tf32(sc[0][2 * th + 0], aq[0][kk], b0, b1);
                mma_tf32(sc[0][2 * th + 1], aq[0][kk], b2, b3);
                mma_tf32(sc[1][2 * th + 0], aq[1][kk], b0, b1);
                mma_tf32(sc[1][2 * th + 1], aq[1][kk], b2, b3);
            }
        }

        // ---- Online softmax + P stores, per m-tile ----
#pragma unroll
        for (int mb = 0; mb < 2; mb++) {
            float rm0 = -1e30f, rm1 = -1e30f;
#pragma unroll
            for (int t = 0; t < 8; t++) {
                rm0 = fmaxf(rm0, fmaxf(sc[mb][t][0], sc[mb][t][1]));
                rm1 = fmaxf(rm1, fmaxf(sc[mb][t][2], sc[mb][t][3]));
            }
            rm0 = fmaxf(rm0, __shfl_xor_sync(0xffffffffu, rm0, 1));
            rm0 = fmaxf(rm0, __shfl_xor_sync(0xffffffffu, rm0, 2));
            rm1 = fmaxf(rm1, __shfl_xor_sync(0xffffffffu, rm1, 1));
            rm1 = fmaxf(rm1, __shfl_xor_sync(0xffffffffu, rm1, 2));

            float mn0 = fmaxf(m0[mb], rm0), mn1 = fmaxf(m1[mb], rm1);
            float al0 = __expf(m0[mb] - mn0), al1 = __expf(m1[mb] - mn1);
            float s0 = 0.f, s1 = 0.f;
#pragma unroll
            for (int t = 0; t < 8; t++) {
                sc[mb][t][0] = __expf(sc[mb][t][0] - mn0);
                sc[mb][t][1] = __expf(sc[mb][t][1] - mn0);
                sc[mb][t][2] = __expf(sc[mb][t][2] - mn1);
                sc[mb][t][3] = __expf(sc[mb][t][3] - mn1);
                s0 += sc[mb][t][0] + sc[mb][t][1];
                s1 += sc[mb][t][2] + sc[mb][t][3];
            }
            s0 += __shfl_xor_sync(0xffffffffu, s0, 1);
            s0 += __shfl_xor_sync(0xffffffffu, s0, 2);
            s1 += __shfl_xor_sync(0xffffffffu, s1, 1);
            s1 += __shfl_xor_sync(0xffffffffu, s1, 2);
            l0[mb] = l0[mb] * al0 + s0;  m0[mb] = mn0;
            l1[mb] = l1[mb] * al1 + s1;  m1[mb] = mn1;
#pragma unroll
            for (int t = 0; t < 8; t++) {
                o[mb][t][0] *= al0; o[mb][t][1] *= al0;
                o[mb][t][2] *= al1; o[mb][t][3] *= al1;
            }

            // Store P rows (mb*16 + g) and (mb*16 + g + 8), swizzled
#pragma unroll
            for (int t = 0; t < 8; t++) {
                int col = (t << 3) + (q << 1);
                int ch = col >> 2, cl = col & 3;
                int r0 = (mb << 4) + g;
                int a0 = (r0 << 6) + ((ch ^ (r0 & 15)) << 2) + cl;
                Pw[a0] = f2tf(sc[mb][t][0]);  Pw[a0 + 1] = f2tf(sc[mb][t][1]);
                int r1 = r0 + 8;
                int a1 = (r1 << 6) + ((ch ^ (r1 & 15)) << 2) + cl;
                Pw[a1] = f2tf(sc[mb][t][2]);  Pw[a1 + 1] = f2tf(sc[mb][t][3]);
            }
        }
        __syncwarp();

        // ---- O += P @ V : each V fragment feeds both m-tiles ----
#pragma unroll
        for (int kk = 0; kk < 8; kk++) {
            uint32_t ap[2][4];
            const int ch = (kk << 1) + (tp >> 1);
#pragma unroll
            for (int mb = 0; mb < 2; mb++) {
                int row = (mb << 4) + pa_row;
                uint32_t addr = pwb + (((row << 6) + ((ch ^ (row & 15)) << 2)) << 2);
                ldsm_x4(ap[mb][0], ap[mb][1], ap[mb][2], ap[mb][3], addr);
            }
#pragma unroll
            for (int t = 0; t < 8; t++) {
                int n = (t << 3) + g;
                int vch = n >> 2, cl = n & 3;
                int k0 = (kk << 3) + q, k1 = k0 + 4;
                uint32_t b0 = Vs[(k0 << 6) + ((vch ^ (k0 & 15)) << 2) + cl];
                uint32_t b1 = Vs[(k1 << 6) + ((vch ^ (k1 & 15)) << 2) + cl];
                mma_tf32(o[0][t], ap[0], b0, b1);
                mma_tf32(o[1][t], ap[1], b0, b1);
            }
        }
    }

    // ---- Epilogue ----
#pragma unroll
    for (int mb = 0; mb < 2; mb++) {
        float inv0 = 1.0f / l0[mb], inv1 = 1.0f / l1[mb];
        float* O0 = O + (size_t)(rowW + (mb << 4) + g) * DMODEL + head * HD;
        float* O1 = O0 + 8 * DMODEL;
#pragma unroll
        for (int t = 0; t < 8; t++) {
            int col = (t << 3) + (q << 1);
            *(float2*)(O0 + col) = make_float2(o[mb][t][0] * inv0, o[mb][t][1] * inv0);
            *(float2*)(O1 + col) = make_float2(o[mb][t][2] * inv1, o[mb][t][3] * inv1);
        }
    }
}

// ============================================================================
// kernel_launch
// ============================================================================
extern "C" void kernel_launch(void* const* d_in, const int* in_sizes, int n_in,
                              void* d_out, int out_size)
{
    const float* q  = (const float*)d_in[0];
    const float* k  = (const float*)d_in[1];
    const float* v  = (const float*)d_in[2];
    const float* Wq = (const float*)d_in[3];
    const float* Wk = (const float*)d_in[4];
    const float* Wv = (const float*)d_in[5];
    const float* Wo = (const float*)d_in[6];
    const float* bo = (const float*)d_in[7];

    const int S = in_sizes[0] / DMODEL;   // 4096

    float *pQ, *pK, *pV, *pAO, *pT1;
    cudaGetSymbolAddress((void**)&pQ,  g_Q);
    cudaGetSymbolAddress((void**)&pK,  g_K);
    cudaGetSymbolAddress((void**)&pV,  g_V);
    cudaGetSymbolAddress((void**)&pAO, g_AO);
    cudaGetSymbolAddress((void**)&pT1, g_T1);

    dim3 gp(DMODEL / 128, S / 128);   // (4, 32)
    dim3 blk(256);

    // Projections (tf32 tensor cores)
    gemm_tc_kernel<<<gp, blk>>>(q, Wq, pQ, nullptr, S, DMODEL, DMODEL);
    gemm_tc_kernel<<<gp, blk>>>(k, Wk, pK, nullptr, S, DMODEL, DMODEL);
    gemm_tc_kernel<<<gp, blk>>>(v, Wv, pV, nullptr, S, DMODEL, DMODEL);

    // Attention (tf32 tensor cores, 64KB dynamic smem)
    static bool attr_set = false;
    if (!attr_set) {
        cudaFuncSetAttribute(attn_tc_kernel,
                             cudaFuncAttributeMaxDynamicSharedMemorySize, 65536);
        attr_set = true;
    }
    dim3 ga(S / 128, NHEAD);          // (32, 8)
    attn_tc_kernel<<<ga, dim3(128), 65536>>>(pQ, pK, pV, pAO, S);

    // Output projection applied twice (tf32 tensor cores)
    gemm_tc_kernel<<<gp, blk>>>(pAO, Wo, pT1, bo, S, DMODEL, DMODEL);
    gemm_tc_kernel<<<gp, blk>>>(pT1, Wo, (float*)d_out, bo, S, DMODEL, DMODEL);
}

// round 6
// speedup vs baseline: 4.2943x; 1.0268x over previous
#include <cuda_runtime.h>
#include <math.h>
#include <stdint.h>

#define DMODEL 512
#define NHEAD 8
#define HD 64
#define MAXS 4096

// Scratch (no allocations allowed) — __device__ globals.
__device__ float g_Q[MAXS * DMODEL];
__device__ float g_K[MAXS * DMODEL];
__device__ float g_V[MAXS * DMODEL];
__device__ float g_AO[MAXS * DMODEL];
__device__ float g_T1[MAXS * DMODEL];

__device__ __forceinline__ uint32_t f2tf(float f) {
    uint32_t u;
    asm("cvt.rna.tf32.f32 %0, %1;" : "=r"(u) : "f"(f));
    return u;
}

__device__ __forceinline__ void mma_tf32(float* c, const uint32_t* a,
                                         uint32_t b0, uint32_t b1) {
    asm volatile(
        "mma.sync.aligned.m16n8k8.row.col.f32.tf32.tf32.f32 "
        "{%0,%1,%2,%3}, {%4,%5,%6,%7}, {%8,%9}, {%0,%1,%2,%3};\n"
        : "+f"(c[0]), "+f"(c[1]), "+f"(c[2]), "+f"(c[3])
        : "r"(a[0]), "r"(a[1]), "r"(a[2]), "r"(a[3]), "r"(b0), "r"(b1));
}

__device__ __forceinline__ void ldsm_x4(uint32_t& r0, uint32_t& r1,
                                        uint32_t& r2, uint32_t& r3,
                                        uint32_t addr) {
    asm volatile("ldmatrix.sync.aligned.m8n8.x4.shared.b16 {%0,%1,%2,%3}, [%4];"
                 : "=r"(r0), "=r"(r1), "=r"(r2), "=r"(r3) : "r"(addr));
}

__device__ __forceinline__ uint32_t s2u(const void* p) {
    return (uint32_t)__cvta_generic_to_shared(p);
}

__device__ __forceinline__ void cp_async16(uint32_t smem_addr, const void* gptr) {
    asm volatile("cp.async.ca.shared.global [%0], [%1], 16;"
                 :: "r"(smem_addr), "l"(gptr));
}
__device__ __forceinline__ void cp_commit() {
    asm volatile("cp.async.commit_group;");
}
template <int N>
__device__ __forceinline__ void cp_wait() {
    asm volatile("cp.async.wait_group %0;" :: "n"(N));
}

// ============================================================================
// tf32 tensor-core GEMM with software pipeline:
// B fragments prefetched one ks-step ahead (fp32 regs, cvt at use),
// A tile double-buffered through registers across the k0 boundary.
// 256 threads = 8 warps (4m x 2n), block tile 128x128, BK=16.
// ============================================================================
__global__ __launch_bounds__(256, 2) void gemm_tc_kernel(
    const float* __restrict__ A, const float* __restrict__ B,
    float* __restrict__ C, const float* __restrict__ bias,
    int M, int N, int K)
{
    __shared__ uint32_t As[128 * 16];

    const int tid = threadIdx.x;
    const int w = tid >> 5, lane = tid & 31;
    const int g = lane >> 2, q = lane & 3;
    const int wm = w >> 1, wn = w & 1;
    const int bm = blockIdx.y << 7, bn = blockIdx.x << 7;
    const int n0 = bn + (wn << 6);

    float acc[2][8][4];
#pragma unroll
    for (int mb = 0; mb < 2; mb++)
#pragma unroll
        for (int t = 0; t < 8; t++)
#pragma unroll
            for (int i = 0; i < 4; i++) acc[mb][t][i] = 0.f;

    const uint32_t asb = s2u(As);
    const int tp = lane >> 3;
    const int arow_l = ((tp & 1) << 3) + (lane & 7);
    const int asw = (arow_l >> 1) & 3;

    const int fr = tid >> 2;              // 0..63
    const int fcc = tid & 3;              // chunk 0..3
    const int fc = fcc << 2;              // col word

    // Prefetch A tile k0=0 into registers
    float4 aReg0 = *(const float4*)(A + (size_t)(bm + fr) * K + fc);
    float4 aReg1 = *(const float4*)(A + (size_t)(bm + fr + 64) * K + fc);

    // Prefetch B fragments for (k0=0, ks=0)
    float br[8][2];
    {
        const float* bp0 = B + (size_t)q * N + n0 + g;
#pragma unroll
        for (int t = 0; t < 8; t++) {
            br[t][0] = __ldg(bp0 + (t << 3));
            br[t][1] = __ldg(bp0 + (t << 3) + 4 * N);
        }
    }

    for (int k0 = 0; k0 < K; k0 += 16) {
        __syncthreads();
        // store prefetched A regs (cvt to tf32, swizzled)
        {
            uint32_t* d0 = &As[(fr << 4) + ((fcc ^ ((fr >> 1) & 3)) << 2)];
            *(uint4*)d0 = make_uint4(f2tf(aReg0.x), f2tf(aReg0.y),
                                     f2tf(aReg0.z), f2tf(aReg0.w));
            int fr1 = fr + 64;
            uint32_t* d1 = &As[(fr1 << 4) + ((fcc ^ ((fr1 >> 1) & 3)) << 2)];
            *(uint4*)d1 = make_uint4(f2tf(aReg1.x), f2tf(aReg1.y),
                                     f2tf(aReg1.z), f2tf(aReg1.w));
        }
        __syncthreads();

        const bool more = (k0 + 16) < K;
        if (more) {
            aReg0 = *(const float4*)(A + (size_t)(bm + fr) * K + k0 + 16 + fc);
            aReg1 = *(const float4*)(A + (size_t)(bm + fr + 64) * K + k0 + 16 + fc);
        }

#pragma unroll
        for (int ks = 0; ks < 2; ks++) {
            // convert current B fragments
            uint32_t bf[8][2];
#pragma unroll
            for (int t = 0; t < 8; t++) {
                bf[t][0] = f2tf(br[t][0]);
                bf[t][1] = f2tf(br[t][1]);
            }
            // prefetch next B fragments (stay in flight during MMAs)
            int knext = (ks == 0) ? (k0 + 8) : (more ? (k0 + 16) : 0);
            {
                const float* bpn = B + (size_t)(knext + q) * N + n0 + g;
#pragma unroll
                for (int t = 0; t < 8; t++) {
                    br[t][0] = __ldg(bpn + (t << 3));
                    br[t][1] = __ldg(bpn + (t << 3) + 4 * N);
                }
            }
            // A fragments via ldmatrix
            uint32_t a[2][4];
#pragma unroll
            for (int mb = 0; mb < 2; mb++) {
                int r = (wm << 5) + (mb << 4) + arow_l;
                int ch = (ks << 1) + (tp >> 1);
                uint32_t addr = asb + (((r << 4) + ((ch ^ asw) << 2)) << 2);
                ldsm_x4(a[mb][0], a[mb][1], a[mb][2], a[mb][3], addr);
            }
#pragma unroll
            for (int mb = 0; mb < 2; mb++)
#pragma unroll
                for (int t = 0; t < 8; t++)
                    mma_tf32(acc[mb][t], a[mb], bf[t][0], bf[t][1]);
        }
    }

#pragma unroll
    for (int mb = 0; mb < 2; mb++) {
        int row = bm + (wm << 5) + (mb << 4) + g;
#pragma unroll
        for (int t = 0; t < 8; t++) {
            int col = n0 + (t << 3) + (q << 1);
            float b0 = 0.f, b1 = 0.f;
            if (bias) { b0 = bias[col]; b1 = bias[col + 1]; }
            *(float2*)(C + (size_t)row * N + col) =
                make_float2(acc[mb][t][0] + b0, acc[mb][t][1] + b1);
            *(float2*)(C + (size_t)(row + 8) * N + col) =
                make_float2(acc[mb][t][2] + b0, acc[mb][t][3] + b1);
        }
    }
}

// ============================================================================
// Flash attention, tf32 mma, 32 q-rows/warp, DOUBLE-BUFFERED cp.async K/V.
// Smem (96KB dynamic): Kbuf 2x16KB | Vbuf 2x16KB | Ps 32KB.
// K/V stored raw fp32 (swizzled); converted to tf32 post-load (fma pipe idle).
// ============================================================================
__global__ __launch_bounds__(128, 2) void attn_tc_kernel(
    const float* __restrict__ Q, const float* __restrict__ K,
    const float* __restrict__ V, float* __restrict__ O, int S)
{
    extern __shared__ uint32_t sh[];
    // words: K buffers [0,8192), V buffers [8192,16384), P [16384,24576)
    uint32_t* Ps = sh + 16384;

    const int tid = threadIdx.x;
    const int w = tid >> 5, lane = tid & 31;
    const int g = lane >> 2, q = lane & 3;
    const int head = blockIdx.y;
    const int q0 = blockIdx.x << 7;
    const int rowW = q0 + (w << 5);

    const int tp = lane >> 3;
    const int kb_row = ((tp >> 1) << 3) + (lane & 7);
    const int pa_row = ((tp & 1) << 3) + (lane & 7);

    const uint32_t shb = s2u(sh);
    const uint32_t pwb = shb + (16384 << 2) + (w << 13);
    uint32_t* Pw = Ps + (w << 11);

    const float* Kg0 = K + head * HD;
    const float* Vg0 = V + head * HD;

    // ---- Q fragments (scaled, tf32), 2 m-tiles x 8 k-steps ----
    uint32_t aq[2][8][4];
#pragma unroll
    for (int mb = 0; mb < 2; mb++) {
        const float* Q0 = Q + (size_t)(rowW + (mb << 4) + g) * DMODEL + head * HD;
        const float* Q1 = Q0 + 8 * DMODEL;
#pragma unroll
        for (int kk = 0; kk < 8; kk++) {
            aq[mb][kk][0] = f2tf(Q0[8 * kk + q] * 0.125f);
            aq[mb][kk][1] = f2tf(Q1[8 * kk + q] * 0.125f);
            aq[mb][kk][2] = f2tf(Q0[8 * kk + q + 4] * 0.125f);
            aq[mb][kk][3] = f2tf(Q1[8 * kk + q + 4] * 0.125f);
        }
    }

    float o[2][8][4];
#pragma unroll
    for (int mb = 0; mb < 2; mb++)
#pragma unroll
        for (int t = 0; t < 8; t++)
#pragma unroll
            for (int i = 0; i < 4; i++) o[mb][t][i] = 0.f;
    float m0[2] = { -1e30f, -1e30f }, m1[2] = { -1e30f, -1e30f };
    float l0[2] = { 0.f, 0.f }, l1[2] = { 0.f, 0.f };

    const int nkb = S >> 6;

    // ---- async stage of tile kb into buffer buf ----
    auto stage = [&](int kb, int buf) {
        const float* Kg = Kg0 + (size_t)(kb << 6) * DMODEL;
        const float* Vg = Vg0 + (size_t)(kb << 6) * DMODEL;
        uint32_t kd = shb + (buf << 14);                 // buf*4096 words
        uint32_t vd = shb + (8192 << 2) + (buf << 14);
#pragma unroll
        for (int f = tid; f < 1024; f += 128) {
            int r = f >> 4, c4 = f & 15;
            uint32_t off = (((r << 6) + ((c4 ^ (r & 15)) << 2)) << 2);
            cp_async16(kd + off, Kg + (size_t)r * DMODEL + (c4 << 2));
            cp_async16(vd + off, Vg + (size_t)r * DMODEL + (c4 << 2));
        }
    };

    stage(0, 0);
    cp_commit();

    for (int kb = 0; kb < nkb; kb++) {
        const int cur = kb & 1;
        if (kb + 1 < nkb) {
            stage(kb + 1, cur ^ 1);   // previous compute's end-sync protects buf
            cp_commit();
            cp_wait<1>();
        } else {
            cp_wait<0>();
        }
        __syncthreads();

        const uint32_t ksb = shb + (cur << 14);
        const uint32_t* Vs = sh + 8192 + (cur << 12);

        // ---- S = Q @ K^T (ldsm raw fp32 -> cvt) ----
        float sc[2][8][4];
#pragma unroll
        for (int mb = 0; mb < 2; mb++)
#pragma unroll
            for (int t = 0; t < 8; t++)
#pragma unroll
                for (int i = 0; i < 4; i++) sc[mb][t][i] = 0.f;

#pragma unroll
        for (int kk = 0; kk < 8; kk++) {
            const int ch = (kk << 1) + (tp & 1);
#pragma unroll
            for (int th = 0; th < 4; th++) {
                int row = (th << 4) + kb_row;
                uint32_t addr = ksb + (((row << 6) + ((ch ^ (row & 15)) << 2)) << 2);
                uint32_t b0, b1, b2, b3;
                ldsm_x4(b0, b1, b2, b3, addr);
                b0 = f2tf(__uint_as_float(b0)); b1 = f2tf(__uint_as_float(b1));
                b2 = f2tf(__uint_as_float(b2)); b3 = f2tf(__uint_as_float(b3));
                mma_tf32(sc[0][2 * th + 0], aq[0][kk], b0, b1);
                mma_tf32(sc[0][2 * th + 1], aq[0][kk], b2, b3);
                mma_tf32(sc[1][2 * th + 0], aq[1][kk], b0, b1);
                mma_tf32(sc[1][2 * th + 1], aq[1][kk], b2, b3);
            }
        }

        // ---- Online softmax + P stores ----
#pragma unroll
        for (int mb = 0; mb < 2; mb++) {
            float rm0 = -1e30f, rm1 = -1e30f;
#pragma unroll
            for (int t = 0; t < 8; t++) {
                rm0 = fmaxf(rm0, fmaxf(sc[mb][t][0], sc[mb][t][1]));
                rm1 = fmaxf(rm1, fmaxf(sc[mb][t][2], sc[mb][t][3]));
            }
            rm0 = fmaxf(rm0, __shfl_xor_sync(0xffffffffu, rm0, 1));
            rm0 = fmaxf(rm0, __shfl_xor_sync(0xffffffffu, rm0, 2));
            rm1 = fmaxf(rm1, __shfl_xor_sync(0xffffffffu, rm1, 1));
            rm1 = fmaxf(rm1, __shfl_xor_sync(0xffffffffu, rm1, 2));

            float mn0 = fmaxf(m0[mb], rm0), mn1 = fmaxf(m1[mb], rm1);
            float al0 = __expf(m0[mb] - mn0), al1 = __expf(m1[mb] - mn1);
            float s0 = 0.f, s1 = 0.f;
#pragma unroll
            for (int t = 0; t < 8; t++) {
                sc[mb][t][0] = __expf(sc[mb][t][0] - mn0);
                sc[mb][t][1] = __expf(sc[mb][t][1] - mn0);
                sc[mb][t][2] = __expf(sc[mb][t][2] - mn1);
                sc[mb][t][3] = __expf(sc[mb][t][3] - mn1);
                s0 += sc[mb][t][0] + sc[mb][t][1];
                s1 += sc[mb][t][2] + sc[mb][t][3];
            }
            s0 += __shfl_xor_sync(0xffffffffu, s0, 1);
            s0 += __shfl_xor_sync(0xffffffffu, s0, 2);
            s1 += __shfl_xor_sync(0xffffffffu, s1, 1);
            s1 += __shfl_xor_sync(0xffffffffu, s1, 2);
            l0[mb] = l0[mb] * al0 + s0;  m0[mb] = mn0;
            l1[mb] = l1[mb] * al1 + s1;  m1[mb] = mn1;
#pragma unroll
            for (int t = 0; t < 8; t++) {
                o[mb][t][0] *= al0; o[mb][t][1] *= al0;
                o[mb][t][2] *= al1; o[mb][t][3] *= al1;
            }

#pragma unroll
            for (int t = 0; t < 8; t++) {
                int col = (t << 3) + (q << 1);
                int ch = col >> 2, cl = col & 3;
                int r0 = (mb << 4) + g;
                int a0 = (r0 << 6) + ((ch ^ (r0 & 15)) << 2) + cl;
                Pw[a0] = f2tf(sc[mb][t][0]);  Pw[a0 + 1] = f2tf(sc[mb][t][1]);
                int r1 = r0 + 8;
                int a1 = (r1 << 6) + ((ch ^ (r1 & 15)) << 2) + cl;
                Pw[a1] = f2tf(sc[mb][t][2]);  Pw[a1 + 1] = f2tf(sc[mb][t][3]);
            }
        }
        __syncwarp();

        // ---- O += P @ V (A-frags ldsm from P; V raw fp32 scalar + cvt) ----
#pragma unroll
        for (int kk = 0; kk < 8; kk++) {
            uint32_t ap[2][4];
            const int ch = (kk << 1) + (tp >> 1);
#pragma unroll
            for (int mb = 0; mb < 2; mb++) {
                int row = (mb << 4) + pa_row;
                uint32_t addr = pwb + (((row << 6) + ((ch ^ (row & 15)) << 2)) << 2);
                ldsm_x4(ap[mb][0], ap[mb][1], ap[mb][2], ap[mb][3], addr);
            }
#pragma unroll
            for (int t = 0; t < 8; t++) {
                int n = (t << 3) + g;
                int vch = n >> 2, cl = n & 3;
                int k0 = (kk << 3) + q, k1 = k0 + 4;
                uint32_t b0 = f2tf(__uint_as_float(
                    Vs[(k0 << 6) + ((vch ^ (k0 & 15)) << 2) + cl]));
                uint32_t b1 = f2tf(__uint_as_float(
                    Vs[(k1 << 6) + ((vch ^ (k1 & 15)) << 2) + cl]));
                mma_tf32(o[0][t], ap[0], b0, b1);
                mma_tf32(o[1][t], ap[1], b0, b1);
            }
        }
        __syncthreads();   // all warps done with cur buffer before reuse
    }

    // ---- Epilogue ----
#pragma unroll
    for (int mb = 0; mb < 2; mb++) {
        float inv0 = 1.0f / l0[mb], inv1 = 1.0f / l1[mb];
        float* O0 = O + (size_t)(rowW + (mb << 4) + g) * DMODEL + head * HD;
        float* O1 = O0 + 8 * DMODEL;
#pragma unroll
        for (int t = 0; t < 8; t++) {
            int col = (t << 3) + (q << 1);
            *(float2*)(O0 + col) = make_float2(o[mb][t][0] * inv0, o[mb][t][1] * inv0);
            *(float2*)(O1 + col) = make_float2(o[mb][t][2] * inv1, o[mb][t][3] * inv1);
        }
    }
}

// ============================================================================
// kernel_launch
// ============================================================================
extern "C" void kernel_launch(void* const* d_in, const int* in_sizes, int n_in,
                              void* d_out, int out_size)
{
    const float* q  = (const float*)d_in[0];
    const float* k  = (const float*)d_in[1];
    const float* v  = (const float*)d_in[2];
    const float* Wq = (const float*)d_in[3];
    const float* Wk = (const float*)d_in[4];
    const float* Wv = (const float*)d_in[5];
    const float* Wo = (const float*)d_in[6];
    const float* bo = (const float*)d_in[7];

    const int S = in_sizes[0] / DMODEL;   // 4096

    float *pQ, *pK, *pV, *pAO, *pT1;
    cudaGetSymbolAddress((void**)&pQ,  g_Q);
    cudaGetSymbolAddress((void**)&pK,  g_K);
    cudaGetSymbolAddress((void**)&pV,  g_V);
    cudaGetSymbolAddress((void**)&pAO, g_AO);
    cudaGetSymbolAddress((void**)&pT1, g_T1);

    dim3 gp(DMODEL / 128, S / 128);   // (4, 32)
    dim3 blk(256);

    // Projections (tf32 tensor cores, pipelined)
    gemm_tc_kernel<<<gp, blk>>>(q, Wq, pQ, nullptr, S, DMODEL, DMODEL);
    gemm_tc_kernel<<<gp, blk>>>(k, Wk, pK, nullptr, S, DMODEL, DMODEL);
    gemm_tc_kernel<<<gp, blk>>>(v, Wv, pV, nullptr, S, DMODEL, DMODEL);

    // Attention (tf32 tensor cores, 96KB dynamic smem, cp.async double buffer)
    static bool attr_set = false;
    if (!attr_set) {
        cudaFuncSetAttribute(attn_tc_kernel,
                             cudaFuncAttributeMaxDynamicSharedMemorySize, 98304);
        attr_set = true;
    }
    dim3 ga(S / 128, NHEAD);          // (32, 8)
    attn_tc_kernel<<<ga, dim3(128), 98304>>>(pQ, pK, pV, pAO, S);

    // Output projection applied twice (tf32 tensor cores)
    gemm_tc_kernel<<<gp, blk>>>(pAO, Wo, pT1, bo, S, DMODEL, DMODEL);
    gemm_tc_kernel<<<gp, blk>>>(pT1, Wo, (float*)d_out, bo, S, DMODEL, DMODEL);
}

// round 7
// speedup vs baseline: 4.5037x; 1.0488x over previous
#include <cuda_runtime.h>
#include <math.h>
#include <stdint.h>

#define DMODEL 512
#define NHEAD 8
#define HD 64
#define MAXS 4096

// Scratch (no allocations allowed) — __device__ globals.
__device__ float g_Q[MAXS * DMODEL];
__device__ float g_K[MAXS * DMODEL];
__device__ float g_V[MAXS * DMODEL];
__device__ float g_AO[MAXS * DMODEL];
__device__ float g_T1[MAXS * DMODEL];

__device__ __forceinline__ uint32_t f2tf(float f) {
    uint32_t u;
    asm("cvt.rna.tf32.f32 %0, %1;" : "=r"(u) : "f"(f));
    return u;
}

__device__ __forceinline__ void mma_tf32(float* c, const uint32_t* a,
                                         uint32_t b0, uint32_t b1) {
    asm volatile(
        "mma.sync.aligned.m16n8k8.row.col.f32.tf32.tf32.f32 "
        "{%0,%1,%2,%3}, {%4,%5,%6,%7}, {%8,%9}, {%0,%1,%2,%3};\n"
        : "+f"(c[0]), "+f"(c[1]), "+f"(c[2]), "+f"(c[3])
        : "r"(a[0]), "r"(a[1]), "r"(a[2]), "r"(a[3]), "r"(b0), "r"(b1));
}

__device__ __forceinline__ void ldsm_x4(uint32_t& r0, uint32_t& r1,
                                        uint32_t& r2, uint32_t& r3,
                                        uint32_t addr) {
    asm volatile("ldmatrix.sync.aligned.m8n8.x4.shared.b16 {%0,%1,%2,%3}, [%4];"
                 : "=r"(r0), "=r"(r1), "=r"(r2), "=r"(r3) : "r"(addr));
}

__device__ __forceinline__ uint32_t s2u(const void* p) {
    return (uint32_t)__cvta_generic_to_shared(p);
}

__device__ __forceinline__ void cp_async16(uint32_t smem_addr, const void* gptr) {
    asm volatile("cp.async.ca.shared.global [%0], [%1], 16;"
                 :: "r"(smem_addr), "l"(gptr));
}
__device__ __forceinline__ void cp_commit() {
    asm volatile("cp.async.commit_group;");
}
template <int N>
__device__ __forceinline__ void cp_wait() {
    asm volatile("cp.async.wait_group %0;" :: "n"(N));
}

// ============================================================================
// tf32 tensor-core GEMM, software pipelined (round 6).
// mode: 0 = plain fp32 out (+bias), 1 = emit tf32-rounded bits,
//       2 = scale by 0.125 then emit tf32-rounded bits (Q projection).
// ============================================================================
__global__ __launch_bounds__(256, 2) void gemm_tc_kernel(
    const float* __restrict__ A, const float* __restrict__ B,
    float* __restrict__ C, const float* __restrict__ bias,
    int M, int N, int K, int mode)
{
    __shared__ uint32_t As[128 * 16];

    const int tid = threadIdx.x;
    const int w = tid >> 5, lane = tid & 31;
    const int g = lane >> 2, q = lane & 3;
    const int wm = w >> 1, wn = w & 1;
    const int bm = blockIdx.y << 7, bn = blockIdx.x << 7;
    const int n0 = bn + (wn << 6);

    float acc[2][8][4];
#pragma unroll
    for (int mb = 0; mb < 2; mb++)
#pragma unroll
        for (int t = 0; t < 8; t++)
#pragma unroll
            for (int i = 0; i < 4; i++) acc[mb][t][i] = 0.f;

    const uint32_t asb = s2u(As);
    const int tp = lane >> 3;
    const int arow_l = ((tp & 1) << 3) + (lane & 7);
    const int asw = (arow_l >> 1) & 3;

    const int fr = tid >> 2;
    const int fcc = tid & 3;
    const int fc = fcc << 2;

    float4 aReg0 = *(const float4*)(A + (size_t)(bm + fr) * K + fc);
    float4 aReg1 = *(const float4*)(A + (size_t)(bm + fr + 64) * K + fc);

    float br[8][2];
    {
        const float* bp0 = B + (size_t)q * N + n0 + g;
#pragma unroll
        for (int t = 0; t < 8; t++) {
            br[t][0] = __ldg(bp0 + (t << 3));
            br[t][1] = __ldg(bp0 + (t << 3) + 4 * N);
        }
    }

    for (int k0 = 0; k0 < K; k0 += 16) {
        __syncthreads();
        {
            uint32_t* d0 = &As[(fr << 4) + ((fcc ^ ((fr >> 1) & 3)) << 2)];
            *(uint4*)d0 = make_uint4(f2tf(aReg0.x), f2tf(aReg0.y),
                                     f2tf(aReg0.z), f2tf(aReg0.w));
            int fr1 = fr + 64;
            uint32_t* d1 = &As[(fr1 << 4) + ((fcc ^ ((fr1 >> 1) & 3)) << 2)];
            *(uint4*)d1 = make_uint4(f2tf(aReg1.x), f2tf(aReg1.y),
                                     f2tf(aReg1.z), f2tf(aReg1.w));
        }
        __syncthreads();

        const bool more = (k0 + 16) < K;
        if (more) {
            aReg0 = *(const float4*)(A + (size_t)(bm + fr) * K + k0 + 16 + fc);
            aReg1 = *(const float4*)(A + (size_t)(bm + fr + 64) * K + k0 + 16 + fc);
        }

#pragma unroll
        for (int ks = 0; ks < 2; ks++) {
            uint32_t bf[8][2];
#pragma unroll
            for (int t = 0; t < 8; t++) {
                bf[t][0] = f2tf(br[t][0]);
                bf[t][1] = f2tf(br[t][1]);
            }
            int knext = (ks == 0) ? (k0 + 8) : (more ? (k0 + 16) : 0);
            {
                const float* bpn = B + (size_t)(knext + q) * N + n0 + g;
#pragma unroll
                for (int t = 0; t < 8; t++) {
                    br[t][0] = __ldg(bpn + (t << 3));
                    br[t][1] = __ldg(bpn + (t << 3) + 4 * N);
                }
            }
            uint32_t a[2][4];
#pragma unroll
            for (int mb = 0; mb < 2; mb++) {
                int r = (wm << 5) + (mb << 4) + arow_l;
                int ch = (ks << 1) + (tp >> 1);
                uint32_t addr = asb + (((r << 4) + ((ch ^ asw) << 2)) << 2);
                ldsm_x4(a[mb][0], a[mb][1], a[mb][2], a[mb][3], addr);
            }
#pragma unroll
            for (int mb = 0; mb < 2; mb++)
#pragma unroll
                for (int t = 0; t < 8; t++)
                    mma_tf32(acc[mb][t], a[mb], bf[t][0], bf[t][1]);
        }
    }

    const float esc = (mode == 2) ? 0.125f : 1.0f;
#pragma unroll
    for (int mb = 0; mb < 2; mb++) {
        int row = bm + (wm << 5) + (mb << 4) + g;
#pragma unroll
        for (int t = 0; t < 8; t++) {
            int col = n0 + (t << 3) + (q << 1);
            float b0 = 0.f, b1 = 0.f;
            if (bias) { b0 = bias[col]; b1 = bias[col + 1]; }
            float2 v0 = make_float2(acc[mb][t][0] + b0, acc[mb][t][1] + b1);
            float2 v1 = make_float2(acc[mb][t][2] + b0, acc[mb][t][3] + b1);
            if (mode) {
                v0.x = __uint_as_float(f2tf(v0.x * esc));
                v0.y = __uint_as_float(f2tf(v0.y * esc));
                v1.x = __uint_as_float(f2tf(v1.x * esc));
                v1.y = __uint_as_float(f2tf(v1.y * esc));
            }
            *(float2*)(C + (size_t)row * N + col) = v0;
            *(float2*)(C + (size_t)(row + 8) * N + col) = v1;
        }
    }
}

// ============================================================================
// Flash attention, tf32 mma, 32 q-rows/warp, cp.async double-buffered K/V.
// Q/K/V arrive ALREADY tf32-rounded (and Q pre-scaled) from the projection
// GEMMs -> zero conversions on the hot K/V/Q paths. Only P converts post-exp.
// Smem (96KB dynamic): Kbuf 2x16KB | Vbuf 2x16KB | Ps 32KB.
// ============================================================================
__global__ __launch_bounds__(128, 2) void attn_tc_kernel(
    const float* __restrict__ Q, const float* __restrict__ K,
    const float* __restrict__ V, float* __restrict__ O, int S)
{
    extern __shared__ uint32_t sh[];
    uint32_t* Ps = sh + 16384;

    const int tid = threadIdx.x;
    const int w = tid >> 5, lane = tid & 31;
    const int g = lane >> 2, q = lane & 3;
    const int head = blockIdx.y;
    const int q0 = blockIdx.x << 7;
    const int rowW = q0 + (w << 5);

    const int tp = lane >> 3;
    const int kb_row = ((tp >> 1) << 3) + (lane & 7);
    const int pa_row = ((tp & 1) << 3) + (lane & 7);

    const uint32_t shb = s2u(sh);
    const uint32_t pwb = shb + (16384 << 2) + (w << 13);
    uint32_t* Pw = Ps + (w << 11);

    const float* Kg0 = K + head * HD;
    const float* Vg0 = V + head * HD;

    // ---- Q fragments: raw bits (already scaled + tf32-rounded) ----
    uint32_t aq[2][8][4];
#pragma unroll
    for (int mb = 0; mb < 2; mb++) {
        const float* Q0 = Q + (size_t)(rowW + (mb << 4) + g) * DMODEL + head * HD;
        const float* Q1 = Q0 + 8 * DMODEL;
#pragma unroll
        for (int kk = 0; kk < 8; kk++) {
            aq[mb][kk][0] = __float_as_uint(Q0[8 * kk + q]);
            aq[mb][kk][1] = __float_as_uint(Q1[8 * kk + q]);
            aq[mb][kk][2] = __float_as_uint(Q0[8 * kk + q + 4]);
            aq[mb][kk][3] = __float_as_uint(Q1[8 * kk + q + 4]);
        }
    }

    float o[2][8][4];
#pragma unroll
    for (int mb = 0; mb < 2; mb++)
#pragma unroll
        for (int t = 0; t < 8; t++)
#pragma unroll
            for (int i = 0; i < 4; i++) o[mb][t][i] = 0.f;
    float m0[2] = { -1e30f, -1e30f }, m1[2] = { -1e30f, -1e30f };
    float l0[2] = { 0.f, 0.f }, l1[2] = { 0.f, 0.f };

    const int nkb = S >> 6;

    auto stage = [&](int kb, int buf) {
        const float* Kg = Kg0 + (size_t)(kb << 6) * DMODEL;
        const float* Vg = Vg0 + (size_t)(kb << 6) * DMODEL;
        uint32_t kd = shb + (buf << 14);
        uint32_t vd = shb + (8192 << 2) + (buf << 14);
#pragma unroll
        for (int f = tid; f < 1024; f += 128) {
            int r = f >> 4, c4 = f & 15;
            uint32_t off = (((r << 6) + ((c4 ^ (r & 15)) << 2)) << 2);
            cp_async16(kd + off, Kg + (size_t)r * DMODEL + (c4 << 2));
            cp_async16(vd + off, Vg + (size_t)r * DMODEL + (c4 << 2));
        }
    };

    stage(0, 0);
    cp_commit();

    for (int kb = 0; kb < nkb; kb++) {
        const int cur = kb & 1;
        if (kb + 1 < nkb) {
            stage(kb + 1, cur ^ 1);
            cp_commit();
            cp_wait<1>();
        } else {
            cp_wait<0>();
        }
        __syncthreads();

        const uint32_t ksb = shb + (cur << 14);
        const uint32_t* Vs = sh + 8192 + (cur << 12);

        // ---- S = Q @ K^T : ldsm feeds mma directly (no cvt) ----
        float sc[2][8][4];
#pragma unroll
        for (int mb = 0; mb < 2; mb++)
#pragma unroll
            for (int t = 0; t < 8; t++)
#pragma unroll
                for (int i = 0; i < 4; i++) sc[mb][t][i] = 0.f;

#pragma unroll
        for (int kk = 0; kk < 8; kk++) {
            const int ch = (kk << 1) + (tp & 1);
#pragma unroll
            for (int th = 0; th < 4; th++) {
                int row = (th << 4) + kb_row;
                uint32_t addr = ksb + (((row << 6) + ((ch ^ (row & 15)) << 2)) << 2);
                uint32_t b0, b1, b2, b3;
                ldsm_x4(b0, b1, b2, b3, addr);
                mma_tf32(sc[0][2 * th + 0], aq[0][kk], b0, b1);
                mma_tf32(sc[0][2 * th + 1], aq[0][kk], b2, b3);
                mma_tf32(sc[1][2 * th + 0], aq[1][kk], b0, b1);
                mma_tf32(sc[1][2 * th + 1], aq[1][kk], b2, b3);
            }
        }

        // ---- Online softmax + P stores ----
#pragma unroll
        for (int mb = 0; mb < 2; mb++) {
            float rm0 = -1e30f, rm1 = -1e30f;
#pragma unroll
            for (int t = 0; t < 8; t++) {
                rm0 = fmaxf(rm0, fmaxf(sc[mb][t][0], sc[mb][t][1]));
                rm1 = fmaxf(rm1, fmaxf(sc[mb][t][2], sc[mb][t][3]));
            }
            rm0 = fmaxf(rm0, __shfl_xor_sync(0xffffffffu, rm0, 1));
            rm0 = fmaxf(rm0, __shfl_xor_sync(0xffffffffu, rm0, 2));
            rm1 = fmaxf(rm1, __shfl_xor_sync(0xffffffffu, rm1, 1));
            rm1 = fmaxf(rm1, __shfl_xor_sync(0xffffffffu, rm1, 2));

            float mn0 = fmaxf(m0[mb], rm0), mn1 = fmaxf(m1[mb], rm1);
            float al0 = __expf(m0[mb] - mn0), al1 = __expf(m1[mb] - mn1);
            float s0 = 0.f, s1 = 0.f;
#pragma unroll
            for (int t = 0; t < 8; t++) {
                sc[mb][t][0] = __expf(sc[mb][t][0] - mn0);
                sc[mb][t][1] = __expf(sc[mb][t][1] - mn0);
                sc[mb][t][2] = __expf(sc[mb][t][2] - mn1);
                sc[mb][t][3] = __expf(sc[mb][t][3] - mn1);
                s0 += sc[mb][t][0] + sc[mb][t][1];
                s1 += sc[mb][t][2] + sc[mb][t][3];
            }
            s0 += __shfl_xor_sync(0xffffffffu, s0, 1);
            s0 += __shfl_xor_sync(0xffffffffu, s0, 2);
            s1 += __shfl_xor_sync(0xffffffffu, s1, 1);
            s1 += __shfl_xor_sync(0xffffffffu, s1, 2);
            l0[mb] = l0[mb] * al0 + s0;  m0[mb] = mn0;
            l1[mb] = l1[mb] * al1 + s1;  m1[mb] = mn1;
#pragma unroll
            for (int t = 0; t < 8; t++) {
                o[mb][t][0] *= al0; o[mb][t][1] *= al0;
                o[mb][t][2] *= al1; o[mb][t][3] *= al1;
            }

#pragma unroll
            for (int t = 0; t < 8; t++) {
                int col = (t << 3) + (q << 1);
                int ch = col >> 2, cl = col & 3;
                int r0 = (mb << 4) + g;
                int a0 = (r0 << 6) + ((ch ^ (r0 & 15)) << 2) + cl;
                Pw[a0] = f2tf(sc[mb][t][0]);  Pw[a0 + 1] = f2tf(sc[mb][t][1]);
                int r1 = r0 + 8;
                int a1 = (r1 << 6) + ((ch ^ (r1 & 15)) << 2) + cl;
                Pw[a1] = f2tf(sc[mb][t][2]);  Pw[a1 + 1] = f2tf(sc[mb][t][3]);
            }
        }
        __syncwarp();

        // ---- O += P @ V (V bits already tf32-rounded: no cvt) ----
#pragma unroll
        for (int kk = 0; kk < 8; kk++) {
            uint32_t ap[2][4];
            const int ch = (kk << 1) + (tp >> 1);
#pragma unroll
            for (int mb = 0; mb < 2; mb++) {
                int row = (mb << 4) + pa_row;
                uint32_t addr = pwb + (((row << 6) + ((ch ^ (row & 15)) << 2)) << 2);
                ldsm_x4(ap[mb][0], ap[mb][1], ap[mb][2], ap[mb][3], addr);
            }
#pragma unroll
            for (int t = 0; t < 8; t++) {
                int n = (t << 3) + g;
                int vch = n >> 2, cl = n & 3;
                int k0 = (kk << 3) + q, k1 = k0 + 4;
                uint32_t b0 = Vs[(k0 << 6) + ((vch ^ (k0 & 15)) << 2) + cl];
                uint32_t b1 = Vs[(k1 << 6) + ((vch ^ (k1 & 15)) << 2) + cl];
                mma_tf32(o[0][t], ap[0], b0, b1);
                mma_tf32(o[1][t], ap[1], b0, b1);
            }
        }
        __syncthreads();
    }

    // ---- Epilogue ----
#pragma unroll
    for (int mb = 0; mb < 2; mb++) {
        float inv0 = 1.0f / l0[mb], inv1 = 1.0f / l1[mb];
        float* O0 = O + (size_t)(rowW + (mb << 4) + g) * DMODEL + head * HD;
        float* O1 = O0 + 8 * DMODEL;
#pragma unroll
        for (int t = 0; t < 8; t++) {
            int col = (t << 3) + (q << 1);
            *(float2*)(O0 + col) = make_float2(o[mb][t][0] * inv0, o[mb][t][1] * inv0);
            *(float2*)(O1 + col) = make_float2(o[mb][t][2] * inv1, o[mb][t][3] * inv1);
        }
    }
}

// ============================================================================
// kernel_launch
// ============================================================================
extern "C" void kernel_launch(void* const* d_in, const int* in_sizes, int n_in,
                              void* d_out, int out_size)
{
    const float* q  = (const float*)d_in[0];
    const float* k  = (const float*)d_in[1];
    const float* v  = (const float*)d_in[2];
    const float* Wq = (const float*)d_in[3];
    const float* Wk = (const float*)d_in[4];
    const float* Wv = (const float*)d_in[5];
    const float* Wo = (const float*)d_in[6];
    const float* bo = (const float*)d_in[7];

    const int S = in_sizes[0] / DMODEL;   // 4096

    float *pQ, *pK, *pV, *pAO, *pT1;
    cudaGetSymbolAddress((void**)&pQ,  g_Q);
    cudaGetSymbolAddress((void**)&pK,  g_K);
    cudaGetSymbolAddress((void**)&pV,  g_V);
    cudaGetSymbolAddress((void**)&pAO, g_AO);
    cudaGetSymbolAddress((void**)&pT1, g_T1);

    dim3 gp(DMODEL / 128, S / 128);   // (4, 32)
    dim3 blk(256);

    // Projections: Q scaled 1/8 + tf32-rounded; K/V tf32-rounded.
    gemm_tc_kernel<<<gp, blk>>>(q, Wq, pQ, nullptr, S, DMODEL, DMODEL, 2);
    gemm_tc_kernel<<<gp, blk>>>(k, Wk, pK, nullptr, S, DMODEL, DMODEL, 1);
    gemm_tc_kernel<<<gp, blk>>>(v, Wv, pV, nullptr, S, DMODEL, DMODEL, 1);

    // Attention (tf32, cp.async double buffer, 96KB dynamic smem)
    static bool attr_set = false;
    if (!attr_set) {
        cudaFuncSetAttribute(attn_tc_kernel,
                             cudaFuncAttributeMaxDynamicSharedMemorySize, 98304);
        attr_set = true;
    }
    dim3 ga(S / 128, NHEAD);          // (32, 8)
    attn_tc_kernel<<<ga, dim3(128), 98304>>>(pQ, pK, pV, pAO, S);

    // Output projection applied twice (plain fp32 out + bias)
    gemm_tc_kernel<<<gp, blk>>>(pAO, Wo, pT1, bo, S, DMODEL, DMODEL, 0);
    gemm_tc_kernel<<<gp, blk>>>(pT1, Wo, (float*)d_out, bo, S, DMODEL, DMODEL, 0);
}

// round 8
// speedup vs baseline: 4.8144x; 1.0690x over previous
#include <cuda_runtime.h>
#include <math.h>
#include <stdint.h>

#define DMODEL 512
#define NHEAD 8
#define HD 64
#define MAXS 4096

// Scratch (no allocations allowed) — __device__ globals.
__device__ float g_Q[MAXS * DMODEL];
__device__ float g_K[MAXS * DMODEL];
__device__ float g_V[MAXS * DMODEL];
__device__ float g_AO[MAXS * DMODEL];
__device__ float g_T1[MAXS * DMODEL];

__device__ __forceinline__ uint32_t f2tf(float f) {
    uint32_t u;
    asm("cvt.rna.tf32.f32 %0, %1;" : "=r"(u) : "f"(f));
    return u;
}

__device__ __forceinline__ void mma_tf32(float* c, const uint32_t* a,
                                         uint32_t b0, uint32_t b1) {
    asm volatile(
        "mma.sync.aligned.m16n8k8.row.col.f32.tf32.tf32.f32 "
        "{%0,%1,%2,%3}, {%4,%5,%6,%7}, {%8,%9}, {%0,%1,%2,%3};\n"
        : "+f"(c[0]), "+f"(c[1]), "+f"(c[2]), "+f"(c[3])
        : "r"(a[0]), "r"(a[1]), "r"(a[2]), "r"(a[3]), "r"(b0), "r"(b1));
}

__device__ __forceinline__ void ldsm_x4(uint32_t& r0, uint32_t& r1,
                                        uint32_t& r2, uint32_t& r3,
                                        uint32_t addr) {
    asm volatile("ldmatrix.sync.aligned.m8n8.x4.shared.b16 {%0,%1,%2,%3}, [%4];"
                 : "=r"(r0), "=r"(r1), "=r"(r2), "=r"(r3) : "r"(addr));
}

__device__ __forceinline__ uint32_t s2u(const void* p) {
    return (uint32_t)__cvta_generic_to_shared(p);
}

__device__ __forceinline__ void cp_async16(uint32_t smem_addr, const void* gptr) {
    asm volatile("cp.async.ca.shared.global [%0], [%1], 16;"
                 :: "r"(smem_addr), "l"(gptr));
}
__device__ __forceinline__ void cp_commit() {
    asm volatile("cp.async.commit_group;");
}
template <int N>
__device__ __forceinline__ void cp_wait() {
    asm volatile("cp.async.wait_group %0;" :: "n"(N));
}

// ============================================================================
// Shared GEMM mainloop body (block tile 128x128, BK=16, 256 thr, pipelined).
// MODE 0: fp32 out + bias; 1: tf32-rounded bits; 2: *0.125 then tf32 bits.
// ============================================================================
template <int MODE>
__device__ __forceinline__ void gemm_body(
    const float* __restrict__ A, const float* __restrict__ B,
    float* __restrict__ C, const float* __restrict__ bias,
    int M, int N, int K, int bm, int bn, uint32_t* As)
{
    const int tid = threadIdx.x;
    const int w = tid >> 5, lane = tid & 31;
    const int g = lane >> 2, q = lane & 3;
    const int wm = w >> 1, wn = w & 1;
    const int n0 = bn + (wn << 6);

    float acc[2][8][4];
#pragma unroll
    for (int mb = 0; mb < 2; mb++)
#pragma unroll
        for (int t = 0; t < 8; t++)
#pragma unroll
            for (int i = 0; i < 4; i++) acc[mb][t][i] = 0.f;

    const uint32_t asb = s2u(As);
    const int tp = lane >> 3;
    const int arow_l = ((tp & 1) << 3) + (lane & 7);
    const int asw = (arow_l >> 1) & 3;

    const int fr = tid >> 2;
    const int fcc = tid & 3;
    const int fc = fcc << 2;

    float4 aReg0 = *(const float4*)(A + (size_t)(bm + fr) * K + fc);
    float4 aReg1 = *(const float4*)(A + (size_t)(bm + fr + 64) * K + fc);

    float br[8][2];
    {
        const float* bp0 = B + (size_t)q * N + n0 + g;
#pragma unroll
        for (int t = 0; t < 8; t++) {
            br[t][0] = __ldg(bp0 + (t << 3));
            br[t][1] = __ldg(bp0 + (t << 3) + 4 * N);
        }
    }

    for (int k0 = 0; k0 < K; k0 += 16) {
        __syncthreads();
        {
            uint32_t* d0 = &As[(fr << 4) + ((fcc ^ ((fr >> 1) & 3)) << 2)];
            *(uint4*)d0 = make_uint4(f2tf(aReg0.x), f2tf(aReg0.y),
                                     f2tf(aReg0.z), f2tf(aReg0.w));
            int fr1 = fr + 64;
            uint32_t* d1 = &As[(fr1 << 4) + ((fcc ^ ((fr1 >> 1) & 3)) << 2)];
            *(uint4*)d1 = make_uint4(f2tf(aReg1.x), f2tf(aReg1.y),
                                     f2tf(aReg1.z), f2tf(aReg1.w));
        }
        __syncthreads();

        const bool more = (k0 + 16) < K;
        if (more) {
            aReg0 = *(const float4*)(A + (size_t)(bm + fr) * K + k0 + 16 + fc);
            aReg1 = *(const float4*)(A + (size_t)(bm + fr + 64) * K + k0 + 16 + fc);
        }

#pragma unroll
        for (int ks = 0; ks < 2; ks++) {
            uint32_t bf[8][2];
#pragma unroll
            for (int t = 0; t < 8; t++) {
                bf[t][0] = f2tf(br[t][0]);
                bf[t][1] = f2tf(br[t][1]);
            }
            int knext = (ks == 0) ? (k0 + 8) : (more ? (k0 + 16) : 0);
            {
                const float* bpn = B + (size_t)(knext + q) * N + n0 + g;
#pragma unroll
                for (int t = 0; t < 8; t++) {
                    br[t][0] = __ldg(bpn + (t << 3));
                    br[t][1] = __ldg(bpn + (t << 3) + 4 * N);
                }
            }
            uint32_t a[2][4];
#pragma unroll
            for (int mb = 0; mb < 2; mb++) {
                int r = (wm << 5) + (mb << 4) + arow_l;
                int ch = (ks << 1) + (tp >> 1);
                uint32_t addr = asb + (((r << 4) + ((ch ^ asw) << 2)) << 2);
                ldsm_x4(a[mb][0], a[mb][1], a[mb][2], a[mb][3], addr);
            }
#pragma unroll
            for (int mb = 0; mb < 2; mb++)
#pragma unroll
                for (int t = 0; t < 8; t++)
                    mma_tf32(acc[mb][t], a[mb], bf[t][0], bf[t][1]);
        }
    }

#pragma unroll
    for (int mb = 0; mb < 2; mb++) {
        int row = bm + (wm << 5) + (mb << 4) + g;
#pragma unroll
        for (int t = 0; t < 8; t++) {
            int col = n0 + (t << 3) + (q << 1);
            float b0 = 0.f, b1 = 0.f;
            if (MODE == 0 && bias) { b0 = bias[col]; b1 = bias[col + 1]; }
            float2 v0 = make_float2(acc[mb][t][0] + b0, acc[mb][t][1] + b1);
            float2 v1 = make_float2(acc[mb][t][2] + b0, acc[mb][t][3] + b1);
            if (MODE == 1) {
                v0.x = __uint_as_float(f2tf(v0.x));
                v0.y = __uint_as_float(f2tf(v0.y));
                v1.x = __uint_as_float(f2tf(v1.x));
                v1.y = __uint_as_float(f2tf(v1.y));
            } else if (MODE == 2) {
                v0.x = __uint_as_float(f2tf(v0.x * 0.125f));
                v0.y = __uint_as_float(f2tf(v0.y * 0.125f));
                v1.x = __uint_as_float(f2tf(v1.x * 0.125f));
                v1.y = __uint_as_float(f2tf(v1.y * 0.125f));
            }
            *(float2*)(C + (size_t)row * N + col) = v0;
            *(float2*)(C + (size_t)(row + 8) * N + col) = v1;
        }
    }
}

// Plain GEMM (Wo projections), fp32 out + bias.
__global__ __launch_bounds__(256, 2) void gemm_tc_kernel(
    const float* __restrict__ A, const float* __restrict__ B,
    float* __restrict__ C, const float* __restrict__ bias,
    int M, int N, int K)
{
    __shared__ uint32_t As[128 * 16];
    gemm_body<0>(A, B, C, bias, M, N, K, blockIdx.y << 7, blockIdx.x << 7, As);
}

// Fused QKV projections: segments pick (A, W, C) triple; one launch, 384 CTAs.
__global__ __launch_bounds__(256, 2) void qkv_gemm_kernel(
    const float* __restrict__ Xq, const float* __restrict__ Xk,
    const float* __restrict__ Xv,
    const float* __restrict__ Wq, const float* __restrict__ Wk,
    const float* __restrict__ Wv,
    float* __restrict__ Qo, float* __restrict__ Ko, float* __restrict__ Vo,
    int M, int K)
{
    __shared__ uint32_t As[128 * 16];
    const int seg = blockIdx.x >> 2;
    const int bn = (blockIdx.x & 3) << 7;
    const int bm = blockIdx.y << 7;
    if (seg == 0)
        gemm_body<2>(Xq, Wq, Qo, nullptr, M, DMODEL, K, bm, bn, As);
    else if (seg == 1)
        gemm_body<1>(Xk, Wk, Ko, nullptr, M, DMODEL, K, bm, bn, As);
    else
        gemm_body<1>(Xv, Wv, Vo, nullptr, M, DMODEL, K, bm, bn, As);
}

// ============================================================================
// Flash attention, tf32 mma, 32 q-rows/warp, cp.async double-buffered K/V.
// Each 64-key tile processed as two 32-key halves to halve the live score
// register set (kills spills at __launch_bounds__(128,2)).
// Smem (96KB dynamic): Kbuf 2x16KB | Vbuf 2x16KB | Ps 32KB.
// ============================================================================
__global__ __launch_bounds__(128, 2) void attn_tc_kernel(
    const float* __restrict__ Q, const float* __restrict__ K,
    const float* __restrict__ V, float* __restrict__ O, int S)
{
    extern __shared__ uint32_t sh[];
    uint32_t* Ps = sh + 16384;

    const int tid = threadIdx.x;
    const int w = tid >> 5, lane = tid & 31;
    const int g = lane >> 2, q = lane & 3;
    const int head = blockIdx.y;
    const int q0 = blockIdx.x << 7;
    const int rowW = q0 + (w << 5);

    const int tp = lane >> 3;
    const int kb_row = ((tp >> 1) << 3) + (lane & 7);
    const int pa_row = ((tp & 1) << 3) + (lane & 7);

    const uint32_t shb = s2u(sh);
    const uint32_t pwb = shb + (16384 << 2) + (w << 13);
    uint32_t* Pw = Ps + (w << 11);

    const float* Kg0 = K + head * HD;
    const float* Vg0 = V + head * HD;

    uint32_t aq[2][8][4];
#pragma unroll
    for (int mb = 0; mb < 2; mb++) {
        const float* Q0 = Q + (size_t)(rowW + (mb << 4) + g) * DMODEL + head * HD;
        const float* Q1 = Q0 + 8 * DMODEL;
#pragma unroll
        for (int kk = 0; kk < 8; kk++) {
            aq[mb][kk][0] = __float_as_uint(Q0[8 * kk + q]);
            aq[mb][kk][1] = __float_as_uint(Q1[8 * kk + q]);
            aq[mb][kk][2] = __float_as_uint(Q0[8 * kk + q + 4]);
            aq[mb][kk][3] = __float_as_uint(Q1[8 * kk + q + 4]);
        }
    }

    float o[2][8][4];
#pragma unroll
    for (int mb = 0; mb < 2; mb++)
#pragma unroll
        for (int t = 0; t < 8; t++)
#pragma unroll
            for (int i = 0; i < 4; i++) o[mb][t][i] = 0.f;
    float m0[2] = { -1e30f, -1e30f }, m1[2] = { -1e30f, -1e30f };
    float l0[2] = { 0.f, 0.f }, l1[2] = { 0.f, 0.f };

    const int nkb = S >> 6;

    auto stage = [&](int kb, int buf) {
        const float* Kg = Kg0 + (size_t)(kb << 6) * DMODEL;
        const float* Vg = Vg0 + (size_t)(kb << 6) * DMODEL;
        uint32_t kd = shb + (buf << 14);
        uint32_t vd = shb + (8192 << 2) + (buf << 14);
#pragma unroll
        for (int f = tid; f < 1024; f += 128) {
            int r = f >> 4, c4 = f & 15;
            uint32_t off = (((r << 6) + ((c4 ^ (r & 15)) << 2)) << 2);
            cp_async16(kd + off, Kg + (size_t)r * DMODEL + (c4 << 2));
            cp_async16(vd + off, Vg + (size_t)r * DMODEL + (c4 << 2));
        }
    };

    stage(0, 0);
    cp_commit();

    for (int kb = 0; kb < nkb; kb++) {
        const int cur = kb & 1;
        if (kb + 1 < nkb) {
            stage(kb + 1, cur ^ 1);
            cp_commit();
            cp_wait<1>();
        } else {
            cp_wait<0>();
        }
        __syncthreads();

        const uint32_t ksb = shb + (cur << 14);
        const uint32_t* Vs = sh + 8192 + (cur << 12);

#pragma unroll
        for (int h = 0; h < 2; h++) {
            float sc[2][4][4];
#pragma unroll
            for (int mb = 0; mb < 2; mb++)
#pragma unroll
                for (int t = 0; t < 4; t++)
#pragma unroll
                    for (int i = 0; i < 4; i++) sc[mb][t][i] = 0.f;

#pragma unroll
            for (int kk = 0; kk < 8; kk++) {
                const int ch = (kk << 1) + (tp & 1);
#pragma unroll
                for (int th = 0; th < 2; th++) {
                    int row = (h << 5) + (th << 4) + kb_row;
                    uint32_t addr = ksb +
                        (((row << 6) + ((ch ^ (row & 15)) << 2)) << 2);
                    uint32_t b0, b1, b2, b3;
                    ldsm_x4(b0, b1, b2, b3, addr);
                    mma_tf32(sc[0][2 * th + 0], aq[0][kk], b0, b1);
                    mma_tf32(sc[0][2 * th + 1], aq[0][kk], b2, b3);
                    mma_tf32(sc[1][2 * th + 0], aq[1][kk], b0, b1);
                    mma_tf32(sc[1][2 * th + 1], aq[1][kk], b2, b3);
                }
            }

#pragma unroll
            for (int mb = 0; mb < 2; mb++) {
                float rm0 = -1e30f, rm1 = -1e30f;
#pragma unroll
                for (int t = 0; t < 4; t++) {
                    rm0 = fmaxf(rm0, fmaxf(sc[mb][t][0], sc[mb][t][1]));
                    rm1 = fmaxf(rm1, fmaxf(sc[mb][t][2], sc[mb][t][3]));
                }
                rm0 = fmaxf(rm0, __shfl_xor_sync(0xffffffffu, rm0, 1));
                rm0 = fmaxf(rm0, __shfl_xor_sync(0xffffffffu, rm0, 2));
                rm1 = fmaxf(rm1, __shfl_xor_sync(0xffffffffu, rm1, 1));
                rm1 = fmaxf(rm1, __shfl_xor_sync(0xffffffffu, rm1, 2));

                float mn0 = fmaxf(m0[mb], rm0), mn1 = fmaxf(m1[mb], rm1);
                float al0 = __expf(m0[mb] - mn0), al1 = __expf(m1[mb] - mn1);
                float s0 = 0.f, s1 = 0.f;
#pragma unroll
                for (int t = 0; t < 4; t++) {
                    sc[mb][t][0] = __expf(sc[mb][t][0] - mn0);
                    sc[mb][t][1] = __expf(sc[mb][t][1] - mn0);
                    sc[mb][t][2] = __expf(sc[mb][t][2] - mn1);
                    sc[mb][t][3] = __expf(sc[mb][t][3] - mn1);
                    s0 += sc[mb][t][0] + sc[mb][t][1];
                    s1 += sc[mb][t][2] + sc[mb][t][3];
                }
                s0 += __shfl_xor_sync(0xffffffffu, s0, 1);
                s0 += __shfl_xor_sync(0xffffffffu, s0, 2);
                s1 += __shfl_xor_sync(0xffffffffu, s1, 1);
                s1 += __shfl_xor_sync(0xffffffffu, s1, 2);
                l0[mb] = l0[mb] * al0 + s0;  m0[mb] = mn0;
                l1[mb] = l1[mb] * al1 + s1;  m1[mb] = mn1;
#pragma unroll
                for (int t = 0; t < 8; t++) {
                    o[mb][t][0] *= al0; o[mb][t][1] *= al0;
                    o[mb][t][2] *= al1; o[mb][t][3] *= al1;
                }

#pragma unroll
                for (int t = 0; t < 4; t++) {
                    int col = (h << 5) + (t << 3) + (q << 1);
                    int ch = col >> 2, cl = col & 3;
                    int r0 = (mb << 4) + g;
                    int a0 = (r0 << 6) + ((ch ^ (r0 & 15)) << 2) + cl;
                    Pw[a0] = f2tf(sc[mb][t][0]);
                    Pw[a0 + 1] = f2tf(sc[mb][t][1]);
                    int r1 = r0 + 8;
                    int a1 = (r1 << 6) + ((ch ^ (r1 & 15)) << 2) + cl;
                    Pw[a1] = f2tf(sc[mb][t][2]);
                    Pw[a1 + 1] = f2tf(sc[mb][t][3]);
                }
            }
            __syncwarp();

#pragma unroll
            for (int kk = 0; kk < 4; kk++) {
                uint32_t ap[2][4];
                const int ch = (h << 3) + (kk << 1) + (tp >> 1);
#pragma unroll
                for (int mb = 0; mb < 2; mb++) {
                    int row = (mb << 4) + pa_row;
                    uint32_t addr = pwb +
                        (((row << 6) + ((ch ^ (row & 15)) << 2)) << 2);
                    ldsm_x4(ap[mb][0], ap[mb][1], ap[mb][2], ap[mb][3], addr);
                }
#pragma unroll
                for (int t = 0; t < 8; t++) {
                    int n = (t << 3) + g;
                    int vch = n >> 2, cl = n & 3;
                    int k0 = (h << 5) + (kk << 3) + q, k1 = k0 + 4;
                    uint32_t b0 = Vs[(k0 << 6) + ((vch ^ (k0 & 15)) << 2) + cl];
                    uint32_t b1 = Vs[(k1 << 6) + ((vch ^ (k1 & 15)) << 2) + cl];
                    mma_tf32(o[0][t], ap[0], b0, b1);
                    mma_tf32(o[1][t], ap[1], b0, b1);
                }
            }
        }
        __syncthreads();
    }

#pragma unroll
    for (int mb = 0; mb < 2; mb++) {
        float inv0 = 1.0f / l0[mb], inv1 = 1.0f / l1[mb];
        float* O0 = O + (size_t)(rowW + (mb << 4) + g) * DMODEL + head * HD;
        float* O1 = O0 + 8 * DMODEL;
#pragma unroll
        for (int t = 0; t < 8; t++) {
            int col = (t << 3) + (q << 1);
            *(float2*)(O0 + col) = make_float2(o[mb][t][0] * inv0, o[mb][t][1] * inv0);
            *(float2*)(O1 + col) = make_float2(o[mb][t][2] * inv1, o[mb][t][3] * inv1);
        }
    }
}

// ============================================================================
// kernel_launch
// ============================================================================
extern "C" void kernel_launch(void* const* d_in, const int* in_sizes, int n_in,
                              void* d_out, int out_size)
{
    const float* q  = (const float*)d_in[0];
    const float* k  = (const float*)d_in[1];
    const float* v  = (const float*)d_in[2];
    const float* Wq = (const float*)d_in[3];
    const float* Wk = (const float*)d_in[4];
    const float* Wv = (const float*)d_in[5];
    const float* Wo = (const float*)d_in[6];
    const float* bo = (const float*)d_in[7];

    const int S = in_sizes[0] / DMODEL;   // 4096

    float *pQ, *pK, *pV, *pAO, *pT1;
    cudaGetSymbolAddress((void**)&pQ,  g_Q);
    cudaGetSymbolAddress((void**)&pK,  g_K);
    cudaGetSymbolAddress((void**)&pV,  g_V);
    cudaGetSymbolAddress((void**)&pAO, g_AO);
    cudaGetSymbolAddress((void**)&pT1, g_T1);

    dim3 blk(256);

    // Fused Q/K/V projections: one 384-CTA launch (Q: *0.125+tf32; K/V: tf32)
    dim3 gq(12, S / 128);             // (12, 32)
    qkv_gemm_kernel<<<gq, blk>>>(q, k, v, Wq, Wk, Wv, pQ, pK, pV, S, DMODEL);

    // Attention (tf32, cp.async double buffer, 96KB dynamic smem)
    static bool attr_set = false;
    if (!attr_set) {
        cudaFuncSetAttribute(attn_tc_kernel,
                             cudaFuncAttributeMaxDynamicSharedMemorySize, 98304);
        attr_set = true;
    }
    dim3 ga(S / 128, NHEAD);          // (32, 8)
    attn_tc_kernel<<<ga, dim3(128), 98304>>>(pQ, pK, pV, pAO, S);

    // Output projection applied twice (plain fp32 out + bias)
    dim3 gp(DMODEL / 128, S / 128);   // (4, 32)
    gemm_tc_kernel<<<gp, blk>>>(pAO, Wo, pT1, bo, S, DMODEL, DMODEL);
    gemm_tc_kernel<<<gp, blk>>>(pT1, Wo, (float*)d_out, bo, S, DMODEL, DMODEL);
}